// round 12
// baseline (speedup 1.0000x reference)
#include <cuda_runtime.h>
#include <cuda_bf16.h>
#include <math.h>
#include <stdint.h>

#define T_LEN   65536
#define HID     256
#define K0PAD   96          // layer-0 K (real 72) padded
#define IN_RAW  72
#define NOUT    1024        // 4*HID interleaved weight rows
#define NH      (T_LEN / 128)   // 512 half-chunks of 128 timesteps

// ======================= scratch =======================
static __device__ __nv_bfloat16  g_A0[(size_t)T_LEN * K0PAD];
static __device__ __nv_bfloat16  g_A1[(size_t)T_LEN * HID];
static __device__ __nv_bfloat16  g_W0[NOUT * K0PAD];
static __device__ __nv_bfloat16  g_W1[NOUT * HID];
static __device__ __nv_bfloat162 g_ab[(size_t)T_LEN * HID];   // (abar, bx) packed
static __device__ __nv_bfloat16  g_c [(size_t)T_LEN * HID];
static __device__ float g_Ph [NH * HID];
static __device__ float g_Sh [NH * HID];
static __device__ float g_Hin[NH * HID];
static __device__ int   g_flag0[NH];
static __device__ int   g_flag1[NH];
static __device__ float g_negA[2 * HID];

__device__ __forceinline__ uint32_t smem_u32(const void* p) {
    uint32_t a;
    asm("{ .reg .u64 t; cvta.to.shared.u64 t, %1; cvt.u32.u64 %0, t; }" : "=r"(a) : "l"(p));
    return a;
}

#define CP16(so, gp) \
    asm volatile("cp.async.cg.shared.global [%0], [%1], 16;" :: "r"(so), "l"(gp) : "memory")
#define CP_COMMIT() asm volatile("cp.async.commit_group;" ::: "memory")
#define CP_WAIT(n)  asm volatile("cp.async.wait_group %0;" :: "n"(n) : "memory")

#define LDSM4(r, addr) \
    asm volatile("ldmatrix.sync.aligned.m8n8.x4.shared.b16 {%0,%1,%2,%3}, [%4];" \
        : "=r"((r)[0]), "=r"((r)[1]), "=r"((r)[2]), "=r"((r)[3]) : "r"(addr))

// non-volatile: lets ptxas schedule/interleave MMAs
#define MMA(d, a, b) \
    asm("mma.sync.aligned.m16n8k16.row.col.f32.bf16.bf16.f32 " \
        "{%0,%1,%2,%3}, {%4,%5,%6,%7}, {%8,%9}, {%0,%1,%2,%3};" \
        : "+f"((d)[0]), "+f"((d)[1]), "+f"((d)[2]), "+f"((d)[3]) \
        : "r"((a)[0]), "r"((a)[1]), "r"((a)[2]), "r"((a)[3]), \
          "r"((b)[0]), "r"((b)[1]))

// ======================= prep =======================
__global__ void prep_w_kernel(const float* __restrict__ Win0, const float* __restrict__ WB0,
                              const float* __restrict__ WC0, const float* __restrict__ Wd0,
                              const float* __restrict__ Win1, const float* __restrict__ WB1,
                              const float* __restrict__ WC1, const float* __restrict__ Wd1) {
    int idx = blockIdx.x * 256 + threadIdx.x;
    if (idx < NOUT * K0PAD) {
        int r = idx / K0PAD, k = idx % K0PAD;
        int h = r >> 2, j = r & 3;
        float v = 0.f;
        if (k < IN_RAW) {
            const float* s = (j == 0) ? Win0 : (j == 1) ? WB0 : (j == 2) ? WC0 : Wd0;
            v = s[h * IN_RAW + k];
        }
        g_W0[idx] = __float2bfloat16(v);
    } else {
        int i2 = idx - NOUT * K0PAD;       // < NOUT*HID
        int r = i2 / HID, k = i2 % HID;
        int h = r >> 2, j = r & 3;
        const float* s = (j == 0) ? Win1 : (j == 1) ? WB1 : (j == 2) ? WC1 : Wd1;
        g_W1[i2] = __float2bfloat16(s[h * HID + k]);
    }
}

__global__ void prep_a_kernel(const float* __restrict__ A0, const float* __restrict__ A1) {
    int h = threadIdx.x;
    g_negA[h] = -expf(A0[h]);
    g_negA[HID + h] = -expf(A1[h]);
    g_flag0[h] = 0;
    g_flag0[h + 256] = 0;
}

__global__ void build_x_kernel(const float* __restrict__ obs, const int* __restrict__ act,
                               const float* __restrict__ emb) {
    int t  = blockIdx.x * 8 + threadIdx.y;
    int k4 = threadIdx.x;                              // 0..23
    float4 v = make_float4(0.f, 0.f, 0.f, 0.f);
    if (k4 < 16) {
        v = *(const float4*)&obs[(size_t)t * 64 + k4 * 4];
    } else if (k4 < 18) {
        int a = act[t];
        v = *(const float4*)&emb[a * 8 + (k4 - 16) * 4];
    }
    __nv_bfloat162 h0 = __float22bfloat162_rn(make_float2(v.x, v.y));
    __nv_bfloat162 h1 = __float22bfloat162_rn(make_float2(v.z, v.w));
    uint2 o = make_uint2(*(uint32_t*)&h0, *(uint32_t*)&h1);
    *(uint2*)&g_A0[(size_t)t * K0PAD + k4 * 4] = o;
}

// ======================= shared GEMM epilogue (CTA = 128M x 64N = 16 channels) =
__device__ __forceinline__ void gate_epilogue(char* smem, float acc[2][4][4],
                                              int tid, int lane, int wm, int wn,
                                              int m0, int bx_, int layer) {
    float* stage = (float*)smem;   // [128][68]
#pragma unroll
    for (int mt = 0; mt < 2; mt++)
#pragma unroll
        for (int nt = 0; nt < 4; nt++) {
            int row = wm * 32 + mt * 16 + (lane >> 2);
            int col = wn * 32 + nt * 8 + (lane & 3) * 2;
            stage[row * 68 + col]           = acc[mt][nt][0];
            stage[row * 68 + col + 1]       = acc[mt][nt][1];
            stage[(row + 8) * 68 + col]     = acc[mt][nt][2];
            stage[(row + 8) * 68 + col + 1] = acc[mt][nt][3];
        }
    __syncthreads();

    const int chl = tid & 15;
    const int rb = tid >> 4;                 // 0..15
    const int chg = bx_ * 16 + chl;
    const float na = g_negA[layer * HID + chg];
#pragma unroll
    for (int i = 0; i < 8; i++) {
        int row = rb + i * 16;
        float4 v = *(const float4*)&stage[row * 68 + chl * 4];  // xs, B, C, d
        float delta = 1.f / (1.f + expf(-v.w));
        float a  = expf(delta * na);
        float bx = v.y * v.x;
        size_t o = (size_t)(m0 + row) * HID + chg;
        g_ab[o] = __floats2bfloat162_rn(a, bx);
        g_c[o]  = __float2bfloat16(v.z);
    }
}

// ======================= layer-0 GEMM: single-shot K=96 =======================
// A 128x96 @208B stride = 26624 | W 64x96 @208B = 13312. 2 syncs total.
#define SMEM0_BYTES 39936

__global__ void __launch_bounds__(256, 3) gemm0_kernel() {
    extern __shared__ __align__(16) char smem[];
    const uint32_t sb = smem_u32(smem);
    const int tid = threadIdx.x, lane = tid & 31;
    const int wm = (tid >> 5) >> 1, wn = (tid >> 5) & 1;
    const int m0 = blockIdx.y * 128, n0 = blockIdx.x * 64;
    const int q = lane >> 3, r = lane & 7;

#pragma unroll
    for (int i = 0; i < 6; i++) {           // A: 128 rows x 12 segs
        int idx = tid + i * 256;
        int row = idx / 12, seg = idx % 12;
        CP16(sb + row * 208 + seg * 16,
             g_A0 + (size_t)(m0 + row) * K0PAD + seg * 8);
    }
#pragma unroll
    for (int i = 0; i < 3; i++) {           // W: 64 rows x 12 segs
        int idx = tid + i * 256;
        int row = idx / 12, seg = idx % 12;
        CP16(sb + 26624 + row * 208 + seg * 16,
             g_W0 + (size_t)(n0 + row) * K0PAD + seg * 8);
    }
    CP_COMMIT();

    const uint32_t aoff = (uint32_t)(wm * 32 + (q & 1) * 8 + r) * 208 + (q >> 1) * 16;
    const uint32_t woff = 26624u + (uint32_t)(wn * 32 + (q >> 1) * 8 + r) * 208 + (q & 1) * 16;

    float acc[2][4][4];
#pragma unroll
    for (int mt = 0; mt < 2; mt++)
#pragma unroll
        for (int nt = 0; nt < 4; nt++)
#pragma unroll
            for (int i = 0; i < 4; i++) acc[mt][nt][i] = 0.f;

    CP_WAIT(0);
    __syncthreads();

#pragma unroll
    for (int ks = 0; ks < 6; ks++) {
        uint32_t ah[2][4];
#pragma unroll
        for (int mt = 0; mt < 2; mt++)
            LDSM4(ah[mt], sb + aoff + (uint32_t)mt * (16 * 208) + ks * 32);
#pragma unroll
        for (int p = 0; p < 2; p++) {
            uint32_t wh[4];
            LDSM4(wh, sb + woff + (uint32_t)p * (16 * 208) + ks * 32);
            const int nt0 = p * 2, nt1 = p * 2 + 1;
            MMA(acc[0][nt0], ah[0], (wh + 0)); MMA(acc[0][nt1], ah[0], (wh + 2));
            MMA(acc[1][nt0], ah[1], (wh + 0)); MMA(acc[1][nt1], ah[1], (wh + 2));
        }
    }
    __syncthreads();

    gate_epilogue(smem, acc, tid, lane, wm, wn, m0, blockIdx.x, 0);
}

// ======================= layer-1 GEMM: BK=64, 2-stage =======================
// stage: A 128x64 @144B = 18432 | W 64x64 @144B = 9216 -> 27648; x2 = 55296.
#define STAGE1_BYTES 27648
#define SMEM1_BYTES  55296

__global__ void __launch_bounds__(256, 3) gemm1_kernel() {
    extern __shared__ __align__(16) char smem[];
    const uint32_t sb = smem_u32(smem);
    const int tid = threadIdx.x, lane = tid & 31;
    const int wm = (tid >> 5) >> 1, wn = (tid >> 5) & 1;
    const int m0 = blockIdx.y * 128, n0 = blockIdx.x * 64;
    const int q = lane >> 3, r = lane & 7;

    const uint32_t aoff = (uint32_t)(wm * 32 + (q & 1) * 8 + r) * 144 + (q >> 1) * 16;
    const uint32_t woff = 18432u + (uint32_t)(wn * 32 + (q >> 1) * 8 + r) * 144 + (q & 1) * 16;

    float acc[2][4][4];
#pragma unroll
    for (int mt = 0; mt < 2; mt++)
#pragma unroll
        for (int nt = 0; nt < 4; nt++)
#pragma unroll
            for (int i = 0; i < 4; i++) acc[mt][nt][i] = 0.f;

    // chunk loader: A 128x8 segs (4/thread), W 64x8 segs (2/thread)
    {
#pragma unroll
        for (int i = 0; i < 4; i++) {
            int idx = tid + i * 256;
            int row = idx >> 3, seg = idx & 7;
            CP16(sb + row * 144 + seg * 16,
                 g_A1 + (size_t)(m0 + row) * HID + seg * 8);
        }
#pragma unroll
        for (int i = 0; i < 2; i++) {
            int idx = tid + i * 256;
            int row = idx >> 3, seg = idx & 7;
            CP16(sb + 18432 + row * 144 + seg * 16,
                 g_W1 + (size_t)(n0 + row) * HID + seg * 8);
        }
        CP_COMMIT();
    }

#pragma unroll
    for (int ck = 0; ck < 4; ck++) {
        CP_WAIT(0);
        __syncthreads();
        if (ck + 1 < 4) {
            uint32_t nb = sb + ((ck + 1) & 1) * STAGE1_BYTES;
            int k0 = (ck + 1) * 64;
#pragma unroll
            for (int i = 0; i < 4; i++) {
                int idx = tid + i * 256;
                int row = idx >> 3, seg = idx & 7;
                CP16(nb + row * 144 + seg * 16,
                     g_A1 + (size_t)(m0 + row) * HID + k0 + seg * 8);
            }
#pragma unroll
            for (int i = 0; i < 2; i++) {
                int idx = tid + i * 256;
                int row = idx >> 3, seg = idx & 7;
                CP16(nb + 18432 + row * 144 + seg * 16,
                     g_W1 + (size_t)(n0 + row) * HID + k0 + seg * 8);
            }
            CP_COMMIT();
        }

        const uint32_t base = sb + (ck & 1) * STAGE1_BYTES;
#pragma unroll
        for (int ks = 0; ks < 4; ks++) {
            uint32_t ah[2][4];
#pragma unroll
            for (int mt = 0; mt < 2; mt++)
                LDSM4(ah[mt], base + aoff + (uint32_t)mt * (16 * 144) + ks * 32);
#pragma unroll
            for (int p = 0; p < 2; p++) {
                uint32_t wh[4];
                LDSM4(wh, base + woff + (uint32_t)p * (16 * 144) + ks * 32);
                const int nt0 = p * 2, nt1 = p * 2 + 1;
                MMA(acc[0][nt0], ah[0], (wh + 0)); MMA(acc[0][nt1], ah[0], (wh + 2));
                MMA(acc[1][nt0], ah[1], (wh + 0)); MMA(acc[1][nt1], ah[1], (wh + 2));
            }
        }
    }
    __syncthreads();

    gate_epilogue(smem, acc, tid, lane, wm, wn, m0, blockIdx.x, 1);
}

// ======================= fused decoupled-lookback scan =======================
__device__ __forceinline__ float lookback_h0(int b, int h, float p, float s,
                                             float* Ph, float* Sh, float* Hin,
                                             int* flag) {
    __shared__ int smf[8];
    float h0 = 0.f;
    if (b > 0) {
        Ph[b * HID + h] = p;
        Sh[b * HID + h] = s;
        __syncthreads();
        __threadfence();
        if (h == 0) atomicExch(&flag[b], 1);

        float Pacc = 1.f, Sacc = 0.f;
        int j = b - 1;
        for (;;) {
            int w = (j + 1 < 8) ? (j + 1) : 8;
            if (h < w) {
                int f;
                do { f = atomicAdd(&flag[j - h], 0); } while (f == 0);
                smf[h] = f;
            }
            __syncthreads();
            int d2 = w;
            for (int d = 0; d < w; d++) if (smf[d] == 2) { d2 = d; break; }
            int nagg = (d2 < w) ? d2 : w;
            for (int d = 0; d < nagg; d++) {
                float P = __ldcg(&Ph[(size_t)(j - d) * HID + h]);
                float S = __ldcg(&Sh[(size_t)(j - d) * HID + h]);
                Sacc = fmaf(Pacc, S, Sacc);
                Pacc *= P;
            }
            if (d2 < w) {
                float H = __ldcg(&Hin[(size_t)(j - d2) * HID + h]);
                h0 = fmaf(Pacc, H, Sacc);
                break;
            }
            j -= w;
            if (j < 0) { h0 = Sacc; break; }
            __syncthreads();
        }
    }
    Hin[b * HID + h] = fmaf(p, h0, s);
    __syncthreads();
    __threadfence();
    if (h == 0) atomicExch(&flag[b], 2);
    return h0;
}

__global__ void __launch_bounds__(256) scan_l0_kernel() {
    int h = threadIdx.x, b = blockIdx.x;
    if (h == 0) atomicExch(&g_flag1[b], 0);
    size_t base = (size_t)b * 128 * HID + h;
    float p = 1.f, s = 0.f;
#pragma unroll 8
    for (int i = 0; i < 128; i++) {
        float2 f = __bfloat1622float2(g_ab[base + (size_t)i * HID]);
        p *= f.x;
        s = fmaf(f.x, s, f.y);
    }
    float hs = lookback_h0(b, h, p, s, g_Ph, g_Sh, g_Hin, g_flag0);
#pragma unroll 8
    for (int i = 0; i < 128; i++) {
        size_t o = base + (size_t)i * HID;
        float2 f = __bfloat1622float2(g_ab[o]);
        hs = fmaf(f.x, hs, f.y);
        g_A1[o] = __float2bfloat16(__bfloat162float(g_c[o]) * hs);
    }
}

__global__ void __launch_bounds__(256) scan_l1_head_kernel(
        const float* __restrict__ Wout, const float* __restrict__ bout,
        float* __restrict__ out) {
    __shared__ float ws[4 * HID];
    __shared__ float bs4[4];
    __shared__ float yt[32][260];
    int tid = threadIdx.x, lane = tid & 31, w = tid >> 5;
    for (int i = tid; i < 4 * HID; i += 256) ws[i] = Wout[i];
    if (tid < 4) bs4[tid] = bout[tid];

    int h = tid, b = blockIdx.x;
    size_t base = (size_t)b * 128 * HID + h;
    float p = 1.f, s = 0.f;
#pragma unroll 8
    for (int i = 0; i < 128; i++) {
        float2 f = __bfloat1622float2(g_ab[base + (size_t)i * HID]);
        p *= f.x;
        s = fmaf(f.x, s, f.y);
    }
    float hs = lookback_h0(b, h, p, s, g_Ph, g_Sh, g_Hin, g_flag1);

    for (int sub = 0; sub < 4; sub++) {
#pragma unroll 8
        for (int j = 0; j < 32; j++) {
            size_t o = base + (size_t)(sub * 32 + j) * HID;
            float2 f = __bfloat1622float2(g_ab[o]);
            hs = fmaf(f.x, hs, f.y);
            yt[j][h] = __bfloat162float(g_c[o]) * hs;
        }
        __syncthreads();
#pragma unroll
        for (int tt = 0; tt < 4; tt++) {
            int tl = w * 4 + tt;
            float a0 = 0.f, a1 = 0.f, a2 = 0.f, a3 = 0.f;
#pragma unroll
            for (int k = 0; k < 8; k++) {
                float v = yt[tl][k * 32 + lane];
                a0 = fmaf(v, ws[0 * HID + k * 32 + lane], a0);
                a1 = fmaf(v, ws[1 * HID + k * 32 + lane], a1);
                a2 = fmaf(v, ws[2 * HID + k * 32 + lane], a2);
                a3 = fmaf(v, ws[3 * HID + k * 32 + lane], a3);
            }
#pragma unroll
            for (int o2 = 16; o2 > 0; o2 >>= 1) {
                a0 += __shfl_down_sync(0xFFFFFFFFu, a0, o2);
                a1 += __shfl_down_sync(0xFFFFFFFFu, a1, o2);
                a2 += __shfl_down_sync(0xFFFFFFFFu, a2, o2);
                a3 += __shfl_down_sync(0xFFFFFFFFu, a3, o2);
            }
            if (lane == 0) {
                float z[4] = {a0 + bs4[0], a1 + bs4[1], a2 + bs4[2], a3 + bs4[3]};
                size_t t = (size_t)b * 128 + sub * 32 + tl;
#pragma unroll
                for (int o3 = 0; o3 < 4; o3++) {
                    float zz = z[o3];
                    float sp = (zz > 20.f) ? zz : log1pf(expf(zz));
                    out[t * 4 + o3] = sp + 1.f;
                }
            }
        }
        __syncthreads();
    }
}

// ======================= launch =======================
extern "C" void kernel_launch(void* const* d_in, const int* in_sizes, int n_in,
                              void* d_out, int out_size) {
    const float* obs   = (const float*)d_in[0];
    const int*   act   = (const int*)  d_in[1];
    const float* emb   = (const float*)d_in[2];
    const float* Win0  = (const float*)d_in[3];
    const float* WB0   = (const float*)d_in[4];
    const float* WC0   = (const float*)d_in[5];
    const float* Wd0   = (const float*)d_in[6];
    const float* Alog0 = (const float*)d_in[7];
    const float* Win1  = (const float*)d_in[8];
    const float* WB1   = (const float*)d_in[9];
    const float* WC1   = (const float*)d_in[10];
    const float* Wd1   = (const float*)d_in[11];
    const float* Alog1 = (const float*)d_in[12];
    const float* Wout  = (const float*)d_in[13];
    const float* bout  = (const float*)d_in[14];
    float* out = (float*)d_out;

    cudaFuncSetAttribute(gemm0_kernel, cudaFuncAttributeMaxDynamicSharedMemorySize, SMEM0_BYTES);
    cudaFuncSetAttribute(gemm1_kernel, cudaFuncAttributeMaxDynamicSharedMemorySize, SMEM1_BYTES);

    prep_w_kernel<<<(NOUT * K0PAD + NOUT * HID) / 256, 256>>>(
        Win0, WB0, WC0, Wd0, Win1, WB1, WC1, Wd1);
    prep_a_kernel<<<1, 256>>>(Alog0, Alog1);
    build_x_kernel<<<T_LEN / 8, dim3(24, 8)>>>(obs, act, emb);

    dim3 ggrid(NOUT / 64, T_LEN / 128);   // (16, 512)

    gemm0_kernel<<<ggrid, 256, SMEM0_BYTES>>>();
    scan_l0_kernel<<<NH, HID>>>();

    gemm1_kernel<<<ggrid, 256, SMEM1_BYTES>>>();
    scan_l1_head_kernel<<<NH, HID>>>(Wout, bout, out);
}

// round 13
// speedup vs baseline: 1.0443x; 1.0443x over previous
#include <cuda_runtime.h>
#include <cuda_bf16.h>
#include <cuda_fp8.h>
#include <math.h>
#include <stdint.h>

#define T_LEN   65536
#define HID     256
#define K0      96          // layer-0 K (real 72) padded, fp8 elements
#define IN_RAW  72
#define NOUT    1024        // 4*HID interleaved weight rows
#define NH      (T_LEN / 128)

#define SA      4.0f        // activation scale
#define SW      16.0f       // weight scale
#define INV_S   (1.0f / (SA * SW))

// ======================= scratch =======================
static __device__ uint8_t        g_A0[(size_t)T_LEN * K0];
static __device__ uint8_t        g_A1[(size_t)T_LEN * HID];
static __device__ uint8_t        g_W0[NOUT * K0];
static __device__ uint8_t        g_W1[NOUT * HID];
static __device__ __nv_bfloat162 g_ab[(size_t)T_LEN * HID];   // (abar, bx) packed
static __device__ __nv_bfloat16  g_c [(size_t)T_LEN * HID];
static __device__ float g_Ph [NH * HID];
static __device__ float g_Sh [NH * HID];
static __device__ float g_Hin[NH * HID];
static __device__ int   g_flag0[NH];
static __device__ int   g_flag1[NH];
static __device__ float g_negA[2 * HID];

__device__ __forceinline__ uint32_t smem_u32(const void* p) {
    uint32_t a;
    asm("{ .reg .u64 t; cvta.to.shared.u64 t, %1; cvt.u32.u64 %0, t; }" : "=r"(a) : "l"(p));
    return a;
}
__device__ __forceinline__ uint8_t to_fp8(float v) {
    return (uint8_t)__nv_cvt_float_to_fp8(v, __NV_SATFINITE, __NV_E4M3);
}

#define CP16(so, gp) \
    asm volatile("cp.async.cg.shared.global [%0], [%1], 16;" :: "r"(so), "l"(gp) : "memory")
#define CP_COMMIT() asm volatile("cp.async.commit_group;" ::: "memory")
#define CP_WAIT(n)  asm volatile("cp.async.wait_group %0;" :: "n"(n) : "memory")

#define LDSM4(r, addr) \
    asm volatile("ldmatrix.sync.aligned.m8n8.x4.shared.b16 {%0,%1,%2,%3}, [%4];" \
        : "=r"((r)[0]), "=r"((r)[1]), "=r"((r)[2]), "=r"((r)[3]) : "r"(addr))

// fp8 e4m3 MMA, K=32 per instruction. Non-volatile: ptxas may schedule.
#define MMA8(d, a, b) \
    asm("mma.sync.aligned.m16n8k32.row.col.f32.e4m3.e4m3.f32 " \
        "{%0,%1,%2,%3}, {%4,%5,%6,%7}, {%8,%9}, {%0,%1,%2,%3};" \
        : "+f"((d)[0]), "+f"((d)[1]), "+f"((d)[2]), "+f"((d)[3]) \
        : "r"((a)[0]), "r"((a)[1]), "r"((a)[2]), "r"((a)[3]), \
          "r"((b)[0]), "r"((b)[1]))

// ======================= prep =======================
__global__ void prep_w_kernel(const float* __restrict__ Win0, const float* __restrict__ WB0,
                              const float* __restrict__ WC0, const float* __restrict__ Wd0,
                              const float* __restrict__ Win1, const float* __restrict__ WB1,
                              const float* __restrict__ WC1, const float* __restrict__ Wd1) {
    int idx = blockIdx.x * 256 + threadIdx.x;
    if (idx < NOUT * K0) {
        int r = idx / K0, k = idx % K0;
        int h = r >> 2, j = r & 3;
        float v = 0.f;
        if (k < IN_RAW) {
            const float* s = (j == 0) ? Win0 : (j == 1) ? WB0 : (j == 2) ? WC0 : Wd0;
            v = s[h * IN_RAW + k];
        }
        g_W0[idx] = to_fp8(v * SW);
    } else {
        int i2 = idx - NOUT * K0;          // < NOUT*HID
        int r = i2 / HID, k = i2 % HID;
        int h = r >> 2, j = r & 3;
        const float* s = (j == 0) ? Win1 : (j == 1) ? WB1 : (j == 2) ? WC1 : Wd1;
        g_W1[i2] = to_fp8(s[h * HID + k] * SW);
    }
}

__global__ void prep_a_kernel(const float* __restrict__ A0, const float* __restrict__ A1) {
    int h = threadIdx.x;
    g_negA[h] = -expf(A0[h]);
    g_negA[HID + h] = -expf(A1[h]);
    g_flag0[h] = 0;
    g_flag0[h + 256] = 0;
}

// thread = 4 consecutive k of one t (4 bytes fp8)
__global__ void build_x_kernel(const float* __restrict__ obs, const int* __restrict__ act,
                               const float* __restrict__ emb) {
    int t  = blockIdx.x * 8 + threadIdx.y;
    int k4 = threadIdx.x;                              // 0..23
    float4 v = make_float4(0.f, 0.f, 0.f, 0.f);
    if (k4 < 16) {
        v = *(const float4*)&obs[(size_t)t * 64 + k4 * 4];
    } else if (k4 < 18) {
        int a = act[t];
        v = *(const float4*)&emb[a * 8 + (k4 - 16) * 4];
    }
    uint32_t o = (uint32_t)to_fp8(v.x * SA) | ((uint32_t)to_fp8(v.y * SA) << 8)
               | ((uint32_t)to_fp8(v.z * SA) << 16) | ((uint32_t)to_fp8(v.w * SA) << 24);
    *(uint32_t*)&g_A0[(size_t)t * K0 + k4 * 4] = o;
}

// ======================= shared GEMM epilogue (CTA = 128M x 64N) ==============
__device__ __forceinline__ void gate_epilogue(char* smem, float acc[2][4][4],
                                              int tid, int lane, int wm, int wn,
                                              int m0, int bx_, int layer) {
    float* stage = (float*)smem;   // [128][68]
#pragma unroll
    for (int mt = 0; mt < 2; mt++)
#pragma unroll
        for (int nt = 0; nt < 4; nt++) {
            int row = wm * 32 + mt * 16 + (lane >> 2);
            int col = wn * 32 + nt * 8 + (lane & 3) * 2;
            stage[row * 68 + col]           = acc[mt][nt][0];
            stage[row * 68 + col + 1]       = acc[mt][nt][1];
            stage[(row + 8) * 68 + col]     = acc[mt][nt][2];
            stage[(row + 8) * 68 + col + 1] = acc[mt][nt][3];
        }
    __syncthreads();

    const int chl = tid & 15;
    const int rb = tid >> 4;
    const int chg = bx_ * 16 + chl;
    const float na = g_negA[layer * HID + chg];
#pragma unroll
    for (int i = 0; i < 8; i++) {
        int row = rb + i * 16;
        float4 v = *(const float4*)&stage[row * 68 + chl * 4];  // xs, B, C, d (scaled)
        float xs = v.x * INV_S, B = v.y * INV_S, C = v.z * INV_S, d = v.w * INV_S;
        float delta = 1.f / (1.f + expf(-d));
        float a  = expf(delta * na);
        float bx = B * xs;
        size_t o = (size_t)(m0 + row) * HID + chg;
        g_ab[o] = __floats2bfloat162_rn(a, bx);
        g_c[o]  = __float2bfloat16(C);
    }
}

// ======================= layer-0 GEMM: single-shot K=96 fp8 ====================
// A 128x96B @112 stride = 14336 | W 64x96B @112 = 7168. Epilogue stage 34816.
#define SMEM0_BYTES 34816

__global__ void __launch_bounds__(256, 3) gemm0_kernel() {
    extern __shared__ __align__(16) char smem[];
    const uint32_t sb = smem_u32(smem);
    const int tid = threadIdx.x, lane = tid & 31;
    const int wm = (tid >> 5) >> 1, wn = (tid >> 5) & 1;
    const int m0 = blockIdx.y * 128, n0 = blockIdx.x * 64;
    const int q = lane >> 3, r = lane & 7;

#pragma unroll
    for (int i = 0; i < 3; i++) {           // A: 128 rows x 6 segs
        int idx = tid + i * 256;
        int row = idx / 6, seg = idx % 6;
        CP16(sb + row * 112 + seg * 16,
             g_A0 + (size_t)(m0 + row) * K0 + seg * 16);
    }
#pragma unroll
    for (int i = 0; i < 2; i++) {           // W: 64 rows x 6 segs = 384
        int idx = tid + i * 256;
        if (idx < 384) {
            int row = idx / 6, seg = idx % 6;
            CP16(sb + 14336 + row * 112 + seg * 16,
                 g_W0 + (size_t)(n0 + row) * K0 + seg * 16);
        }
    }
    CP_COMMIT();

    const uint32_t aoff = (uint32_t)(wm * 32 + (q & 1) * 8 + r) * 112 + (q >> 1) * 16;
    const uint32_t woff = 14336u + (uint32_t)(wn * 32 + (q >> 1) * 8 + r) * 112 + (q & 1) * 16;

    float acc[2][4][4];
#pragma unroll
    for (int mt = 0; mt < 2; mt++)
#pragma unroll
        for (int nt = 0; nt < 4; nt++)
#pragma unroll
            for (int i = 0; i < 4; i++) acc[mt][nt][i] = 0.f;

    CP_WAIT(0);
    __syncthreads();

#pragma unroll
    for (int ks = 0; ks < 3; ks++) {        // k = ks*32 fp8 elements (32 bytes)
        uint32_t ah[2][4];
#pragma unroll
        for (int mt = 0; mt < 2; mt++)
            LDSM4(ah[mt], sb + aoff + (uint32_t)mt * (16 * 112) + ks * 32);
#pragma unroll
        for (int p = 0; p < 2; p++) {
            uint32_t wh[4];
            LDSM4(wh, sb + woff + (uint32_t)p * (16 * 112) + ks * 32);
            const int nt0 = p * 2, nt1 = p * 2 + 1;
            MMA8(acc[0][nt0], ah[0], (wh + 0)); MMA8(acc[0][nt1], ah[0], (wh + 2));
            MMA8(acc[1][nt0], ah[1], (wh + 0)); MMA8(acc[1][nt1], ah[1], (wh + 2));
        }
    }
    __syncthreads();

    gate_epilogue(smem, acc, tid, lane, wm, wn, m0, blockIdx.x, 0);
}

// ======================= layer-1 GEMM: BK=128 fp8, 2-stage ====================
// stage: A 128x128B @144 = 18432 | W 64x128B @144 = 9216 -> 27648; x2 = 55296.
#define STAGE1_BYTES 27648
#define SMEM1_BYTES  55296

__global__ void __launch_bounds__(256, 3) gemm1_kernel() {
    extern __shared__ __align__(16) char smem[];
    const uint32_t sb = smem_u32(smem);
    const int tid = threadIdx.x, lane = tid & 31;
    const int wm = (tid >> 5) >> 1, wn = (tid >> 5) & 1;
    const int m0 = blockIdx.y * 128, n0 = blockIdx.x * 64;
    const int q = lane >> 3, r = lane & 7;

    const uint32_t aoff = (uint32_t)(wm * 32 + (q & 1) * 8 + r) * 144 + (q >> 1) * 16;
    const uint32_t woff = 18432u + (uint32_t)(wn * 32 + (q >> 1) * 8 + r) * 144 + (q & 1) * 16;

    float acc[2][4][4];
#pragma unroll
    for (int mt = 0; mt < 2; mt++)
#pragma unroll
        for (int nt = 0; nt < 4; nt++)
#pragma unroll
            for (int i = 0; i < 4; i++) acc[mt][nt][i] = 0.f;

    // chunk 0 load: A 128 rows x 8 segs, W 64 x 8 segs
    {
#pragma unroll
        for (int i = 0; i < 4; i++) {
            int idx = tid + i * 256;
            int row = idx >> 3, seg = idx & 7;
            CP16(sb + row * 144 + seg * 16,
                 g_A1 + (size_t)(m0 + row) * HID + seg * 16);
        }
#pragma unroll
        for (int i = 0; i < 2; i++) {
            int idx = tid + i * 256;
            int row = idx >> 3, seg = idx & 7;
            CP16(sb + 18432 + row * 144 + seg * 16,
                 g_W1 + (size_t)(n0 + row) * HID + seg * 16);
        }
        CP_COMMIT();
    }

#pragma unroll
    for (int ck = 0; ck < 2; ck++) {
        CP_WAIT(0);
        __syncthreads();
        if (ck == 0) {
            uint32_t nb = sb + STAGE1_BYTES;
#pragma unroll
            for (int i = 0; i < 4; i++) {
                int idx = tid + i * 256;
                int row = idx >> 3, seg = idx & 7;
                CP16(nb + row * 144 + seg * 16,
                     g_A1 + (size_t)(m0 + row) * HID + 128 + seg * 16);
            }
#pragma unroll
            for (int i = 0; i < 2; i++) {
                int idx = tid + i * 256;
                int row = idx >> 3, seg = idx & 7;
                CP16(nb + 18432 + row * 144 + seg * 16,
                     g_W1 + (size_t)(n0 + row) * HID + 128 + seg * 16);
            }
            CP_COMMIT();
        }

        const uint32_t base = sb + ck * STAGE1_BYTES;
#pragma unroll
        for (int ks = 0; ks < 4; ks++) {
            uint32_t ah[2][4];
#pragma unroll
            for (int mt = 0; mt < 2; mt++)
                LDSM4(ah[mt], base + aoff + (uint32_t)mt * (16 * 144) + ks * 32);
#pragma unroll
            for (int p = 0; p < 2; p++) {
                uint32_t wh[4];
                LDSM4(wh, base + woff + (uint32_t)p * (16 * 144) + ks * 32);
                const int nt0 = p * 2, nt1 = p * 2 + 1;
                MMA8(acc[0][nt0], ah[0], (wh + 0)); MMA8(acc[0][nt1], ah[0], (wh + 2));
                MMA8(acc[1][nt0], ah[1], (wh + 0)); MMA8(acc[1][nt1], ah[1], (wh + 2));
            }
        }
    }
    __syncthreads();

    gate_epilogue(smem, acc, tid, lane, wm, wn, m0, blockIdx.x, 1);
}

// ======================= fused decoupled-lookback scan =======================
__device__ __forceinline__ float lookback_h0(int b, int h, float p, float s,
                                             float* Ph, float* Sh, float* Hin,
                                             int* flag) {
    __shared__ int smf[8];
    float h0 = 0.f;
    if (b > 0) {
        Ph[b * HID + h] = p;
        Sh[b * HID + h] = s;
        __syncthreads();
        __threadfence();
        if (h == 0) atomicExch(&flag[b], 1);

        float Pacc = 1.f, Sacc = 0.f;
        int j = b - 1;
        for (;;) {
            int w = (j + 1 < 8) ? (j + 1) : 8;
            if (h < w) {
                int f;
                do { f = atomicAdd(&flag[j - h], 0); } while (f == 0);
                smf[h] = f;
            }
            __syncthreads();
            int d2 = w;
            for (int d = 0; d < w; d++) if (smf[d] == 2) { d2 = d; break; }
            int nagg = (d2 < w) ? d2 : w;
            for (int d = 0; d < nagg; d++) {
                float P = __ldcg(&Ph[(size_t)(j - d) * HID + h]);
                float S = __ldcg(&Sh[(size_t)(j - d) * HID + h]);
                Sacc = fmaf(Pacc, S, Sacc);
                Pacc *= P;
            }
            if (d2 < w) {
                float H = __ldcg(&Hin[(size_t)(j - d2) * HID + h]);
                h0 = fmaf(Pacc, H, Sacc);
                break;
            }
            j -= w;
            if (j < 0) { h0 = Sacc; break; }
            __syncthreads();
        }
    }
    Hin[b * HID + h] = fmaf(p, h0, s);
    __syncthreads();
    __threadfence();
    if (h == 0) atomicExch(&flag[b], 2);
    return h0;
}

__global__ void __launch_bounds__(256) scan_l0_kernel() {
    int h = threadIdx.x, b = blockIdx.x;
    if (h == 0) atomicExch(&g_flag1[b], 0);
    size_t base = (size_t)b * 128 * HID + h;
    float p = 1.f, s = 0.f;
#pragma unroll 8
    for (int i = 0; i < 128; i++) {
        float2 f = __bfloat1622float2(g_ab[base + (size_t)i * HID]);
        p *= f.x;
        s = fmaf(f.x, s, f.y);
    }
    float hs = lookback_h0(b, h, p, s, g_Ph, g_Sh, g_Hin, g_flag0);
#pragma unroll 8
    for (int i = 0; i < 128; i++) {
        size_t o = base + (size_t)i * HID;
        float2 f = __bfloat1622float2(g_ab[o]);
        hs = fmaf(f.x, hs, f.y);
        float y = __bfloat162float(g_c[o]) * hs;
        g_A1[o] = to_fp8(y * SA);
    }
}

__global__ void __launch_bounds__(256) scan_l1_head_kernel(
        const float* __restrict__ Wout, const float* __restrict__ bout,
        float* __restrict__ out) {
    __shared__ float ws[4 * HID];
    __shared__ float bs4[4];
    __shared__ float yt[32][260];
    int tid = threadIdx.x, lane = tid & 31, w = tid >> 5;
    for (int i = tid; i < 4 * HID; i += 256) ws[i] = Wout[i];
    if (tid < 4) bs4[tid] = bout[tid];

    int h = tid, b = blockIdx.x;
    size_t base = (size_t)b * 128 * HID + h;
    float p = 1.f, s = 0.f;
#pragma unroll 8
    for (int i = 0; i < 128; i++) {
        float2 f = __bfloat1622float2(g_ab[base + (size_t)i * HID]);
        p *= f.x;
        s = fmaf(f.x, s, f.y);
    }
    float hs = lookback_h0(b, h, p, s, g_Ph, g_Sh, g_Hin, g_flag1);

    for (int sub = 0; sub < 4; sub++) {
#pragma unroll 8
        for (int j = 0; j < 32; j++) {
            size_t o = base + (size_t)(sub * 32 + j) * HID;
            float2 f = __bfloat1622float2(g_ab[o]);
            hs = fmaf(f.x, hs, f.y);
            yt[j][h] = __bfloat162float(g_c[o]) * hs;
        }
        __syncthreads();
#pragma unroll
        for (int tt = 0; tt < 4; tt++) {
            int tl = w * 4 + tt;
            float a0 = 0.f, a1 = 0.f, a2 = 0.f, a3 = 0.f;
#pragma unroll
            for (int k = 0; k < 8; k++) {
                float v = yt[tl][k * 32 + lane];
                a0 = fmaf(v, ws[0 * HID + k * 32 + lane], a0);
                a1 = fmaf(v, ws[1 * HID + k * 32 + lane], a1);
                a2 = fmaf(v, ws[2 * HID + k * 32 + lane], a2);
                a3 = fmaf(v, ws[3 * HID + k * 32 + lane], a3);
            }
#pragma unroll
            for (int o2 = 16; o2 > 0; o2 >>= 1) {
                a0 += __shfl_down_sync(0xFFFFFFFFu, a0, o2);
                a1 += __shfl_down_sync(0xFFFFFFFFu, a1, o2);
                a2 += __shfl_down_sync(0xFFFFFFFFu, a2, o2);
                a3 += __shfl_down_sync(0xFFFFFFFFu, a3, o2);
            }
            if (lane == 0) {
                float z[4] = {a0 + bs4[0], a1 + bs4[1], a2 + bs4[2], a3 + bs4[3]};
                size_t t = (size_t)b * 128 + sub * 32 + tl;
#pragma unroll
                for (int o3 = 0; o3 < 4; o3++) {
                    float zz = z[o3];
                    float sp = (zz > 20.f) ? zz : log1pf(expf(zz));
                    out[t * 4 + o3] = sp + 1.f;
                }
            }
        }
        __syncthreads();
    }
}

// ======================= launch =======================
extern "C" void kernel_launch(void* const* d_in, const int* in_sizes, int n_in,
                              void* d_out, int out_size) {
    const float* obs   = (const float*)d_in[0];
    const int*   act   = (const int*)  d_in[1];
    const float* emb   = (const float*)d_in[2];
    const float* Win0  = (const float*)d_in[3];
    const float* WB0   = (const float*)d_in[4];
    const float* WC0   = (const float*)d_in[5];
    const float* Wd0   = (const float*)d_in[6];
    const float* Alog0 = (const float*)d_in[7];
    const float* Win1  = (const float*)d_in[8];
    const float* WB1   = (const float*)d_in[9];
    const float* WC1   = (const float*)d_in[10];
    const float* Wd1   = (const float*)d_in[11];
    const float* Alog1 = (const float*)d_in[12];
    const float* Wout  = (const float*)d_in[13];
    const float* bout  = (const float*)d_in[14];
    float* out = (float*)d_out;

    cudaFuncSetAttribute(gemm0_kernel, cudaFuncAttributeMaxDynamicSharedMemorySize, SMEM0_BYTES);
    cudaFuncSetAttribute(gemm1_kernel, cudaFuncAttributeMaxDynamicSharedMemorySize, SMEM1_BYTES);

    prep_w_kernel<<<(NOUT * K0 + NOUT * HID) / 256, 256>>>(
        Win0, WB0, WC0, Wd0, Win1, WB1, WC1, Wd1);
    prep_a_kernel<<<1, 256>>>(Alog0, Alog1);
    build_x_kernel<<<T_LEN / 8, dim3(24, 8)>>>(obs, act, emb);

    dim3 ggrid(NOUT / 64, T_LEN / 128);   // (16, 512)

    gemm0_kernel<<<ggrid, 256, SMEM0_BYTES>>>();
    scan_l0_kernel<<<NH, HID>>>();

    gemm1_kernel<<<ggrid, 256, SMEM1_BYTES>>>();
    scan_l1_head_kernel<<<NH, HID>>>(Wout, bout, out);
}

// round 14
// speedup vs baseline: 1.0759x; 1.0302x over previous
#include <cuda_runtime.h>
#include <cuda_bf16.h>
#include <cuda_fp8.h>
#include <math.h>
#include <stdint.h>

#define T_LEN   65536
#define HID     256
#define K0      96          // layer-0 K (real 72) padded, fp8 elements
#define IN_RAW  72
#define NOUT    1024
#define NH      (T_LEN / 128)

#define SA      4.0f
#define SW      16.0f
#define INV_S   (1.0f / (SA * SW))

// ======================= scratch =======================
static __device__ uint8_t        g_A0[(size_t)T_LEN * K0];
static __device__ uint8_t        g_A1[(size_t)T_LEN * HID];
static __device__ uint8_t        g_W0[NOUT * K0];
static __device__ uint8_t        g_W1[NOUT * HID];
static __device__ __nv_bfloat162 g_ab[(size_t)T_LEN * HID];
static __device__ __nv_bfloat16  g_c [(size_t)T_LEN * HID];
static __device__ float g_Ph [NH * HID];
static __device__ float g_Sh [NH * HID];
static __device__ float g_Hin[NH * HID];
static __device__ int   g_flag0[NH];
static __device__ int   g_flag1[NH];
static __device__ float g_negA[2 * HID];

__device__ __forceinline__ uint32_t smem_u32(const void* p) {
    uint32_t a;
    asm("{ .reg .u64 t; cvta.to.shared.u64 t, %1; cvt.u32.u64 %0, t; }" : "=r"(a) : "l"(p));
    return a;
}
__device__ __forceinline__ uint8_t to_fp8(float v) {
    return (uint8_t)__nv_cvt_float_to_fp8(v, __NV_SATFINITE, __NV_E4M3);
}

#define CP16(so, gp) \
    asm volatile("cp.async.cg.shared.global [%0], [%1], 16;" :: "r"(so), "l"(gp) : "memory")
#define CP_COMMIT() asm volatile("cp.async.commit_group;" ::: "memory")
#define CP_WAIT(n)  asm volatile("cp.async.wait_group %0;" :: "n"(n) : "memory")

#define LDSM4(r, addr) \
    asm volatile("ldmatrix.sync.aligned.m8n8.x4.shared.b16 {%0,%1,%2,%3}, [%4];" \
        : "=r"((r)[0]), "=r"((r)[1]), "=r"((r)[2]), "=r"((r)[3]) : "r"(addr))

#define MMA8(d, a, b) \
    asm("mma.sync.aligned.m16n8k32.row.col.f32.e4m3.e4m3.f32 " \
        "{%0,%1,%2,%3}, {%4,%5,%6,%7}, {%8,%9}, {%0,%1,%2,%3};" \
        : "+f"((d)[0]), "+f"((d)[1]), "+f"((d)[2]), "+f"((d)[3]) \
        : "r"((a)[0]), "r"((a)[1]), "r"((a)[2]), "r"((a)[3]), \
          "r"((b)[0]), "r"((b)[1]))

// ======================= prep =======================
__global__ void prep_w_kernel(const float* __restrict__ Win0, const float* __restrict__ WB0,
                              const float* __restrict__ WC0, const float* __restrict__ Wd0,
                              const float* __restrict__ Win1, const float* __restrict__ WB1,
                              const float* __restrict__ WC1, const float* __restrict__ Wd1) {
    int idx = blockIdx.x * 256 + threadIdx.x;
    if (idx < NOUT * K0) {
        int r = idx / K0, k = idx % K0;
        int h = r >> 2, j = r & 3;
        float v = 0.f;
        if (k < IN_RAW) {
            const float* s = (j == 0) ? Win0 : (j == 1) ? WB0 : (j == 2) ? WC0 : Wd0;
            v = s[h * IN_RAW + k];
        }
        g_W0[idx] = to_fp8(v * SW);
    } else {
        int i2 = idx - NOUT * K0;
        int r = i2 / HID, k = i2 % HID;
        int h = r >> 2, j = r & 3;
        const float* s = (j == 0) ? Win1 : (j == 1) ? WB1 : (j == 2) ? WC1 : Wd1;
        g_W1[i2] = to_fp8(s[h * HID + k] * SW);
    }
}

__global__ void prep_a_kernel(const float* __restrict__ A0, const float* __restrict__ A1) {
    int h = threadIdx.x;
    g_negA[h] = -expf(A0[h]);
    g_negA[HID + h] = -expf(A1[h]);
    g_flag0[h] = 0;
    g_flag0[h + 256] = 0;
}

__global__ void build_x_kernel(const float* __restrict__ obs, const int* __restrict__ act,
                               const float* __restrict__ emb) {
    int t  = blockIdx.x * 8 + threadIdx.y;
    int k4 = threadIdx.x;                              // 0..23
    float4 v = make_float4(0.f, 0.f, 0.f, 0.f);
    if (k4 < 16) {
        v = *(const float4*)&obs[(size_t)t * 64 + k4 * 4];
    } else if (k4 < 18) {
        int a = act[t];
        v = *(const float4*)&emb[a * 8 + (k4 - 16) * 4];
    }
    uint32_t o = (uint32_t)to_fp8(v.x * SA) | ((uint32_t)to_fp8(v.y * SA) << 8)
               | ((uint32_t)to_fp8(v.z * SA) << 16) | ((uint32_t)to_fp8(v.w * SA) << 24);
    *(uint32_t*)&g_A0[(size_t)t * K0 + k4 * 4] = o;
}

// fast gate: delta = sigmoid(d), a = exp(delta*na), all descaled
__device__ __forceinline__ void gate_store(float xs_s, float B_s, float C_s, float d_s,
                                           float na, size_t o) {
    float xs = xs_s * INV_S, B = B_s * INV_S, C = C_s * INV_S, d = d_s * INV_S;
    float delta = __fdividef(1.f, 1.f + __expf(-d));
    float a  = __expf(delta * na);
    g_ab[o] = __floats2bfloat162_rn(a, B * xs);
    g_c[o]  = __float2bfloat16(C);
}

// ======================= layer-0 GEMM: persistent M-loop, K=96 ================
// SMEM: W 64x96B @112 = 7168 | A bufs 2 x (128x96B @112 = 14336) | stage 128x68 f32
#define A0OFF   7168
#define ST0OFF  35840
#define SMEM0_BYTES 70656

__device__ __forceinline__ void g0_load_A(uint32_t sb, int m0, int tid, int buf) {
    uint32_t dst = sb + A0OFF + buf * 14336;
#pragma unroll
    for (int i = 0; i < 3; i++) {
        int idx = tid + i * 256;
        int row = idx / 6, seg = idx % 6;
        CP16(dst + row * 112 + seg * 16, g_A0 + (size_t)(m0 + row) * K0 + seg * 16);
    }
    CP_COMMIT();
}

__global__ void __launch_bounds__(256, 3) gemm0_kernel() {
    extern __shared__ __align__(16) char smem[];
    const uint32_t sb = smem_u32(smem);
    const int tid = threadIdx.x, lane = tid & 31;
    const int wm = (tid >> 5) >> 1, wn = (tid >> 5) & 1;
    const int n0 = blockIdx.x * 64;
    const int mbase = blockIdx.y * 1024;
    const int q = lane >> 3, r = lane & 7;

    // W load (with A(0) in group 0)
#pragma unroll
    for (int i = 0; i < 2; i++) {
        int idx = tid + i * 256;
        if (idx < 384) {
            int row = idx / 6, seg = idx % 6;
            CP16(sb + row * 112 + seg * 16, g_W0 + (size_t)(n0 + row) * K0 + seg * 16);
        }
    }
    g0_load_A(sb, mbase, tid, 0);           // group 0 (W + A0)
    g0_load_A(sb, mbase + 128, tid, 1);     // group 1 (A1)

    const uint32_t aoff = (uint32_t)(wm * 32 + (q & 1) * 8 + r) * 112 + (q >> 1) * 16;
    const uint32_t woff = (uint32_t)(wn * 32 + (q >> 1) * 8 + r) * 112 + (q & 1) * 16;
    const int chl = tid & 15;
    const int rb = tid >> 4;
    const int chg = blockIdx.x * 16 + chl;
    const float na = g_negA[chg];
    float* stage = (float*)(smem + ST0OFF);

    for (int mi = 0; mi < 8; mi++) {
        const int m0 = mbase + mi * 128;
        if (mi == 7) { CP_WAIT(0); } else { CP_WAIT(1); }
        __syncthreads();                    // A(mi) ready; prev stage consumed

        float acc[2][4][4];
#pragma unroll
        for (int mt = 0; mt < 2; mt++)
#pragma unroll
            for (int nt = 0; nt < 4; nt++)
#pragma unroll
                for (int i = 0; i < 4; i++) acc[mt][nt][i] = 0.f;

        const uint32_t abase = sb + A0OFF + (mi & 1) * 14336;
#pragma unroll
        for (int ks = 0; ks < 3; ks++) {
            uint32_t ah[2][4];
#pragma unroll
            for (int mt = 0; mt < 2; mt++)
                LDSM4(ah[mt], abase + aoff + (uint32_t)mt * (16 * 112) + ks * 32);
#pragma unroll
            for (int p = 0; p < 2; p++) {
                uint32_t wh[4];
                LDSM4(wh, sb + woff + (uint32_t)p * (16 * 112) + ks * 32);
                const int nt0 = p * 2, nt1 = p * 2 + 1;
                MMA8(acc[0][nt0], ah[0], (wh + 0)); MMA8(acc[0][nt1], ah[0], (wh + 2));
                MMA8(acc[1][nt0], ah[1], (wh + 0)); MMA8(acc[1][nt1], ah[1], (wh + 2));
            }
        }

        // stage write
#pragma unroll
        for (int mt = 0; mt < 2; mt++)
#pragma unroll
            for (int nt = 0; nt < 4; nt++) {
                int row = wm * 32 + mt * 16 + (lane >> 2);
                int col = wn * 32 + nt * 8 + (lane & 3) * 2;
                stage[row * 68 + col]           = acc[mt][nt][0];
                stage[row * 68 + col + 1]       = acc[mt][nt][1];
                stage[(row + 8) * 68 + col]     = acc[mt][nt][2];
                stage[(row + 8) * 68 + col + 1] = acc[mt][nt][3];
            }
        __syncthreads();                    // LDSMs + stage done

        if (mi + 2 < 8) g0_load_A(sb, mbase + (mi + 2) * 128, tid, mi & 1);

#pragma unroll
        for (int i = 0; i < 8; i++) {
            int row = rb + i * 16;
            float4 v = *(const float4*)&stage[row * 68 + chl * 4];
            gate_store(v.x, v.y, v.z, v.w, na, (size_t)(m0 + row) * HID + chg);
        }
    }
}

// ======================= layer-1 GEMM: persistent M-loop, K=256 ===============
// SMEM: W 64x256B @272 = 17408 | A bufs 2 x (128x256B @272 = 34816) | half stage 64x68
#define A1OFF   17408
#define ST1OFF  87040
#define SMEM1_BYTES 104448

__device__ __forceinline__ void g1_load_A(uint32_t sb, int m0, int tid, int buf) {
    uint32_t dst = sb + A1OFF + buf * 34816;
#pragma unroll
    for (int i = 0; i < 8; i++) {
        int idx = tid + i * 256;
        int row = idx >> 4, seg = idx & 15;
        CP16(dst + row * 272 + seg * 16, g_A1 + (size_t)(m0 + row) * HID + seg * 16);
    }
    CP_COMMIT();
}

__global__ void __launch_bounds__(256, 2) gemm1_kernel() {
    extern __shared__ __align__(16) char smem[];
    const uint32_t sb = smem_u32(smem);
    const int tid = threadIdx.x, lane = tid & 31;
    const int wm = (tid >> 5) >> 1, wn = (tid >> 5) & 1;
    const int n0 = blockIdx.x * 64;
    const int mbase = blockIdx.y * 1024;
    const int q = lane >> 3, r = lane & 7;

    // W load
#pragma unroll
    for (int i = 0; i < 4; i++) {
        int idx = tid + i * 256;
        int row = idx >> 4, seg = idx & 15;
        CP16(sb + row * 272 + seg * 16, g_W1 + (size_t)(n0 + row) * HID + seg * 16);
    }
    g1_load_A(sb, mbase, tid, 0);
    g1_load_A(sb, mbase + 128, tid, 1);

    const uint32_t aoff = (uint32_t)(wm * 32 + (q & 1) * 8 + r) * 272 + (q >> 1) * 16;
    const uint32_t woff = (uint32_t)(wn * 32 + (q >> 1) * 8 + r) * 272 + (q & 1) * 16;
    const int chl = tid & 15;
    const int rb = tid >> 4;
    const int chg = blockIdx.x * 16 + chl;
    const float na = g_negA[HID + chg];
    float* stage = (float*)(smem + ST1OFF);
    const int whalf = wm >> 1;              // warp's stage half

    for (int mi = 0; mi < 8; mi++) {
        const int m0 = mbase + mi * 128;
        if (mi == 7) { CP_WAIT(0); } else { CP_WAIT(1); }
        __syncthreads();

        float acc[2][4][4];
#pragma unroll
        for (int mt = 0; mt < 2; mt++)
#pragma unroll
            for (int nt = 0; nt < 4; nt++)
#pragma unroll
                for (int i = 0; i < 4; i++) acc[mt][nt][i] = 0.f;

        const uint32_t abase = sb + A1OFF + (mi & 1) * 34816;
#pragma unroll
        for (int ks = 0; ks < 8; ks++) {
            uint32_t ah[2][4];
#pragma unroll
            for (int mt = 0; mt < 2; mt++)
                LDSM4(ah[mt], abase + aoff + (uint32_t)mt * (16 * 272) + ks * 32);
#pragma unroll
            for (int p = 0; p < 2; p++) {
                uint32_t wh[4];
                LDSM4(wh, sb + woff + (uint32_t)p * (16 * 272) + ks * 32);
                const int nt0 = p * 2, nt1 = p * 2 + 1;
                MMA8(acc[0][nt0], ah[0], (wh + 0)); MMA8(acc[0][nt1], ah[0], (wh + 2));
                MMA8(acc[1][nt0], ah[1], (wh + 0)); MMA8(acc[1][nt1], ah[1], (wh + 2));
            }
        }

        // epilogue in two 64-row halves
#pragma unroll
        for (int hhalf = 0; hhalf < 2; hhalf++) {
            if (whalf == hhalf) {
#pragma unroll
                for (int mt = 0; mt < 2; mt++)
#pragma unroll
                    for (int nt = 0; nt < 4; nt++) {
                        int row = (wm & 1) * 32 + mt * 16 + (lane >> 2);
                        int col = wn * 32 + nt * 8 + (lane & 3) * 2;
                        stage[row * 68 + col]           = acc[mt][nt][0];
                        stage[row * 68 + col + 1]       = acc[mt][nt][1];
                        stage[(row + 8) * 68 + col]     = acc[mt][nt][2];
                        stage[(row + 8) * 68 + col + 1] = acc[mt][nt][3];
                    }
            }
            __syncthreads();
            if (hhalf == 0 && mi + 2 < 8)
                g1_load_A(sb, mbase + (mi + 2) * 128, tid, mi & 1);
#pragma unroll
            for (int i = 0; i < 4; i++) {
                int row = rb + i * 16;
                float4 v = *(const float4*)&stage[row * 68 + chl * 4];
                gate_store(v.x, v.y, v.z, v.w, na,
                           (size_t)(m0 + hhalf * 64 + row) * HID + chg);
            }
            __syncthreads();
        }
    }
}

// ======================= fused decoupled-lookback scan =======================
__device__ __forceinline__ float lookback_h0(int b, int h, float p, float s,
                                             float* Ph, float* Sh, float* Hin,
                                             int* flag) {
    __shared__ int smf[8];
    float h0 = 0.f;
    if (b > 0) {
        Ph[b * HID + h] = p;
        Sh[b * HID + h] = s;
        __syncthreads();
        __threadfence();
        if (h == 0) atomicExch(&flag[b], 1);

        float Pacc = 1.f, Sacc = 0.f;
        int j = b - 1;
        for (;;) {
            int w = (j + 1 < 8) ? (j + 1) : 8;
            if (h < w) {
                int f;
                do { f = atomicAdd(&flag[j - h], 0); } while (f == 0);
                smf[h] = f;
            }
            __syncthreads();
            int d2 = w;
            for (int d = 0; d < w; d++) if (smf[d] == 2) { d2 = d; break; }
            int nagg = (d2 < w) ? d2 : w;
            for (int d = 0; d < nagg; d++) {
                float P = __ldcg(&Ph[(size_t)(j - d) * HID + h]);
                float S = __ldcg(&Sh[(size_t)(j - d) * HID + h]);
                Sacc = fmaf(Pacc, S, Sacc);
                Pacc *= P;
            }
            if (d2 < w) {
                float H = __ldcg(&Hin[(size_t)(j - d2) * HID + h]);
                h0 = fmaf(Pacc, H, Sacc);
                break;
            }
            j -= w;
            if (j < 0) { h0 = Sacc; break; }
            __syncthreads();
        }
    }
    Hin[b * HID + h] = fmaf(p, h0, s);
    __syncthreads();
    __threadfence();
    if (h == 0) atomicExch(&flag[b], 2);
    return h0;
}

__global__ void __launch_bounds__(256) scan_l0_kernel() {
    int h = threadIdx.x, b = blockIdx.x;
    if (h == 0) atomicExch(&g_flag1[b], 0);
    size_t base = (size_t)b * 128 * HID + h;
    float p = 1.f, s = 0.f;
#pragma unroll 8
    for (int i = 0; i < 128; i++) {
        float2 f = __bfloat1622float2(g_ab[base + (size_t)i * HID]);
        p *= f.x;
        s = fmaf(f.x, s, f.y);
    }
    float hs = lookback_h0(b, h, p, s, g_Ph, g_Sh, g_Hin, g_flag0);
#pragma unroll 8
    for (int i = 0; i < 128; i++) {
        size_t o = base + (size_t)i * HID;
        float2 f = __bfloat1622float2(g_ab[o]);
        hs = fmaf(f.x, hs, f.y);
        float y = __bfloat162float(g_c[o]) * hs;
        g_A1[o] = to_fp8(y * SA);
    }
}

__global__ void __launch_bounds__(256) scan_l1_head_kernel(
        const float* __restrict__ Wout, const float* __restrict__ bout,
        float* __restrict__ out) {
    __shared__ float ws[4 * HID];
    __shared__ float bs4[4];
    __shared__ float yt[32][260];
    int tid = threadIdx.x, lane = tid & 31, w = tid >> 5;
    for (int i = tid; i < 4 * HID; i += 256) ws[i] = Wout[i];
    if (tid < 4) bs4[tid] = bout[tid];

    int h = tid, b = blockIdx.x;
    size_t base = (size_t)b * 128 * HID + h;
    float p = 1.f, s = 0.f;
#pragma unroll 8
    for (int i = 0; i < 128; i++) {
        float2 f = __bfloat1622float2(g_ab[base + (size_t)i * HID]);
        p *= f.x;
        s = fmaf(f.x, s, f.y);
    }
    float hs = lookback_h0(b, h, p, s, g_Ph, g_Sh, g_Hin, g_flag1);

    for (int sub = 0; sub < 4; sub++) {
#pragma unroll 8
        for (int j = 0; j < 32; j++) {
            size_t o = base + (size_t)(sub * 32 + j) * HID;
            float2 f = __bfloat1622float2(g_ab[o]);
            hs = fmaf(f.x, hs, f.y);
            yt[j][h] = __bfloat162float(g_c[o]) * hs;
        }
        __syncthreads();
#pragma unroll
        for (int tt = 0; tt < 4; tt++) {
            int tl = w * 4 + tt;
            float a0 = 0.f, a1 = 0.f, a2 = 0.f, a3 = 0.f;
#pragma unroll
            for (int k = 0; k < 8; k++) {
                float v = yt[tl][k * 32 + lane];
                a0 = fmaf(v, ws[0 * HID + k * 32 + lane], a0);
                a1 = fmaf(v, ws[1 * HID + k * 32 + lane], a1);
                a2 = fmaf(v, ws[2 * HID + k * 32 + lane], a2);
                a3 = fmaf(v, ws[3 * HID + k * 32 + lane], a3);
            }
#pragma unroll
            for (int o2 = 16; o2 > 0; o2 >>= 1) {
                a0 += __shfl_down_sync(0xFFFFFFFFu, a0, o2);
                a1 += __shfl_down_sync(0xFFFFFFFFu, a1, o2);
                a2 += __shfl_down_sync(0xFFFFFFFFu, a2, o2);
                a3 += __shfl_down_sync(0xFFFFFFFFu, a3, o2);
            }
            if (lane == 0) {
                float z[4] = {a0 + bs4[0], a1 + bs4[1], a2 + bs4[2], a3 + bs4[3]};
                size_t t = (size_t)b * 128 + sub * 32 + tl;
#pragma unroll
                for (int o3 = 0; o3 < 4; o3++) {
                    float zz = z[o3];
                    float sp = (zz > 20.f) ? zz : log1pf(expf(zz));
                    out[t * 4 + o3] = sp + 1.f;
                }
            }
        }
        __syncthreads();
    }
}

// ======================= launch =======================
extern "C" void kernel_launch(void* const* d_in, const int* in_sizes, int n_in,
                              void* d_out, int out_size) {
    const float* obs   = (const float*)d_in[0];
    const int*   act   = (const int*)  d_in[1];
    const float* emb   = (const float*)d_in[2];
    const float* Win0  = (const float*)d_in[3];
    const float* WB0   = (const float*)d_in[4];
    const float* WC0   = (const float*)d_in[5];
    const float* Wd0   = (const float*)d_in[6];
    const float* Alog0 = (const float*)d_in[7];
    const float* Win1  = (const float*)d_in[8];
    const float* WB1   = (const float*)d_in[9];
    const float* WC1   = (const float*)d_in[10];
    const float* Wd1   = (const float*)d_in[11];
    const float* Alog1 = (const float*)d_in[12];
    const float* Wout  = (const float*)d_in[13];
    const float* bout  = (const float*)d_in[14];
    float* out = (float*)d_out;

    cudaFuncSetAttribute(gemm0_kernel, cudaFuncAttributeMaxDynamicSharedMemorySize, SMEM0_BYTES);
    cudaFuncSetAttribute(gemm1_kernel, cudaFuncAttributeMaxDynamicSharedMemorySize, SMEM1_BYTES);

    prep_w_kernel<<<(NOUT * K0 + NOUT * HID) / 256, 256>>>(
        Win0, WB0, WC0, Wd0, Win1, WB1, WC1, Wd1);
    prep_a_kernel<<<1, 256>>>(Alog0, Alog1);
    build_x_kernel<<<T_LEN / 8, dim3(24, 8)>>>(obs, act, emb);

    dim3 ggrid(16, 64);   // 16 n-blocks x 64 m-groups (8 tiles each)

    gemm0_kernel<<<ggrid, 256, SMEM0_BYTES>>>();
    scan_l0_kernel<<<NH, HID>>>();

    gemm1_kernel<<<ggrid, 256, SMEM1_BYTES>>>();
    scan_l1_head_kernel<<<NH, HID>>>(Wout, bout, out);
}

// round 15
// speedup vs baseline: 1.0833x; 1.0069x over previous
#include <cuda_runtime.h>
#include <cuda_bf16.h>
#include <cuda_fp8.h>
#include <math.h>
#include <stdint.h>

#define T_LEN   65536
#define HID     256
#define K0      96          // layer-0 K (real 72) padded, fp8 elements
#define IN_RAW  72
#define NOUT    1024
#define NH      (T_LEN / 128)

#define SA      4.0f
#define SW      16.0f
#define INV_S   (1.0f / (SA * SW))

// ======================= scratch =======================
static __device__ uint8_t        g_A0[(size_t)T_LEN * K0];
static __device__ uint8_t        g_A1[(size_t)T_LEN * HID];
static __device__ uint8_t        g_W0[NOUT * K0];
static __device__ uint8_t        g_W1[NOUT * HID];
static __device__ __nv_bfloat162 g_ab[(size_t)T_LEN * HID];
static __device__ __nv_bfloat16  g_c [(size_t)T_LEN * HID];
static __device__ float g_Ph [NH * HID];
static __device__ float g_Sh [NH * HID];
static __device__ float g_Hin[NH * HID];
static __device__ int   g_flag0[NH];
static __device__ int   g_flag1[NH];
static __device__ float g_negA[2 * HID];

__device__ __forceinline__ uint32_t smem_u32(const void* p) {
    uint32_t a;
    asm("{ .reg .u64 t; cvta.to.shared.u64 t, %1; cvt.u32.u64 %0, t; }" : "=r"(a) : "l"(p));
    return a;
}
__device__ __forceinline__ uint8_t to_fp8(float v) {
    return (uint8_t)__nv_cvt_float_to_fp8(v, __NV_SATFINITE, __NV_E4M3);
}

#define CP16(so, gp) \
    asm volatile("cp.async.cg.shared.global [%0], [%1], 16;" :: "r"(so), "l"(gp) : "memory")
#define CP_COMMIT() asm volatile("cp.async.commit_group;" ::: "memory")
#define CP_WAIT(n)  asm volatile("cp.async.wait_group %0;" :: "n"(n) : "memory")

#define LDSM4(r, addr) \
    asm volatile("ldmatrix.sync.aligned.m8n8.x4.shared.b16 {%0,%1,%2,%3}, [%4];" \
        : "=r"((r)[0]), "=r"((r)[1]), "=r"((r)[2]), "=r"((r)[3]) : "r"(addr))

#define MMA8(d, a, b) \
    asm("mma.sync.aligned.m16n8k32.row.col.f32.e4m3.e4m3.f32 " \
        "{%0,%1,%2,%3}, {%4,%5,%6,%7}, {%8,%9}, {%0,%1,%2,%3};" \
        : "+f"((d)[0]), "+f"((d)[1]), "+f"((d)[2]), "+f"((d)[3]) \
        : "r"((a)[0]), "r"((a)[1]), "r"((a)[2]), "r"((a)[3]), \
          "r"((b)[0]), "r"((b)[1]))

// ======================= prep =======================
__global__ void prep_w_kernel(const float* __restrict__ Win0, const float* __restrict__ WB0,
                              const float* __restrict__ WC0, const float* __restrict__ Wd0,
                              const float* __restrict__ Win1, const float* __restrict__ WB1,
                              const float* __restrict__ WC1, const float* __restrict__ Wd1) {
    int idx = blockIdx.x * 256 + threadIdx.x;
    if (idx < NOUT * K0) {
        int r = idx / K0, k = idx % K0;
        int h = r >> 2, j = r & 3;
        float v = 0.f;
        if (k < IN_RAW) {
            const float* s = (j == 0) ? Win0 : (j == 1) ? WB0 : (j == 2) ? WC0 : Wd0;
            v = s[h * IN_RAW + k];
        }
        g_W0[idx] = to_fp8(v * SW);
    } else {
        int i2 = idx - NOUT * K0;
        int r = i2 / HID, k = i2 % HID;
        int h = r >> 2, j = r & 3;
        const float* s = (j == 0) ? Win1 : (j == 1) ? WB1 : (j == 2) ? WC1 : Wd1;
        g_W1[i2] = to_fp8(s[h * HID + k] * SW);
    }
}

__global__ void prep_a_kernel(const float* __restrict__ A0, const float* __restrict__ A1) {
    int h = threadIdx.x;
    g_negA[h] = -expf(A0[h]);
    g_negA[HID + h] = -expf(A1[h]);
    g_flag0[h] = 0;
    g_flag0[h + 256] = 0;
}

__global__ void build_x_kernel(const float* __restrict__ obs, const int* __restrict__ act,
                               const float* __restrict__ emb) {
    int t  = blockIdx.x * 8 + threadIdx.y;
    int k4 = threadIdx.x;                              // 0..23
    float4 v = make_float4(0.f, 0.f, 0.f, 0.f);
    if (k4 < 16) {
        v = *(const float4*)&obs[(size_t)t * 64 + k4 * 4];
    } else if (k4 < 18) {
        int a = act[t];
        v = *(const float4*)&emb[a * 8 + (k4 - 16) * 4];
    }
    uint32_t o = (uint32_t)to_fp8(v.x * SA) | ((uint32_t)to_fp8(v.y * SA) << 8)
               | ((uint32_t)to_fp8(v.z * SA) << 16) | ((uint32_t)to_fp8(v.w * SA) << 24);
    *(uint32_t*)&g_A0[(size_t)t * K0 + k4 * 4] = o;
}

// fast gate epilogue store
__device__ __forceinline__ void gate_store(float xs_s, float B_s, float C_s, float d_s,
                                           float na, size_t o) {
    float xs = xs_s * INV_S, B = B_s * INV_S, C = C_s * INV_S, d = d_s * INV_S;
    float delta = __fdividef(1.f, 1.f + __expf(-d));
    float a  = __expf(delta * na);
    g_ab[o] = __floats2bfloat162_rn(a, B * xs);
    g_c[o]  = __float2bfloat16(C);
}

// ======================= layer-0 GEMM: persistent M-loop, K=96 ================
#define A0OFF   7168
#define ST0OFF  35840
#define SMEM0_BYTES 70656

__device__ __forceinline__ void g0_load_A(uint32_t sb, int m0, int tid, int buf) {
    uint32_t dst = sb + A0OFF + buf * 14336;
#pragma unroll
    for (int i = 0; i < 3; i++) {
        int idx = tid + i * 256;
        int row = idx / 6, seg = idx % 6;
        CP16(dst + row * 112 + seg * 16, g_A0 + (size_t)(m0 + row) * K0 + seg * 16);
    }
    CP_COMMIT();
}

__global__ void __launch_bounds__(256, 3) gemm0_kernel() {
    extern __shared__ __align__(16) char smem[];
    const uint32_t sb = smem_u32(smem);
    const int tid = threadIdx.x, lane = tid & 31;
    const int wm = (tid >> 5) >> 1, wn = (tid >> 5) & 1;
    const int n0 = blockIdx.x * 64;
    const int mbase = blockIdx.y * 1024;
    const int q = lane >> 3, r = lane & 7;

#pragma unroll
    for (int i = 0; i < 2; i++) {
        int idx = tid + i * 256;
        if (idx < 384) {
            int row = idx / 6, seg = idx % 6;
            CP16(sb + row * 112 + seg * 16, g_W0 + (size_t)(n0 + row) * K0 + seg * 16);
        }
    }
    g0_load_A(sb, mbase, tid, 0);
    g0_load_A(sb, mbase + 128, tid, 1);

    const uint32_t aoff = (uint32_t)(wm * 32 + (q & 1) * 8 + r) * 112 + (q >> 1) * 16;
    const uint32_t woff = (uint32_t)(wn * 32 + (q >> 1) * 8 + r) * 112 + (q & 1) * 16;
    const int chl = tid & 15;
    const int rb = tid >> 4;
    const int chg = blockIdx.x * 16 + chl;
    const float na = g_negA[chg];
    float* stage = (float*)(smem + ST0OFF);

    for (int mi = 0; mi < 8; mi++) {
        const int m0 = mbase + mi * 128;
        if (mi == 7) { CP_WAIT(0); } else { CP_WAIT(1); }
        __syncthreads();

        float acc[2][4][4];
#pragma unroll
        for (int mt = 0; mt < 2; mt++)
#pragma unroll
            for (int nt = 0; nt < 4; nt++)
#pragma unroll
                for (int i = 0; i < 4; i++) acc[mt][nt][i] = 0.f;

        const uint32_t abase = sb + A0OFF + (mi & 1) * 14336;
#pragma unroll
        for (int ks = 0; ks < 3; ks++) {
            uint32_t ah[2][4];
#pragma unroll
            for (int mt = 0; mt < 2; mt++)
                LDSM4(ah[mt], abase + aoff + (uint32_t)mt * (16 * 112) + ks * 32);
#pragma unroll
            for (int p = 0; p < 2; p++) {
                uint32_t wh[4];
                LDSM4(wh, sb + woff + (uint32_t)p * (16 * 112) + ks * 32);
                const int nt0 = p * 2, nt1 = p * 2 + 1;
                MMA8(acc[0][nt0], ah[0], (wh + 0)); MMA8(acc[0][nt1], ah[0], (wh + 2));
                MMA8(acc[1][nt0], ah[1], (wh + 0)); MMA8(acc[1][nt1], ah[1], (wh + 2));
            }
        }

#pragma unroll
        for (int mt = 0; mt < 2; mt++)
#pragma unroll
            for (int nt = 0; nt < 4; nt++) {
                int row = wm * 32 + mt * 16 + (lane >> 2);
                int col = wn * 32 + nt * 8 + (lane & 3) * 2;
                stage[row * 68 + col]           = acc[mt][nt][0];
                stage[row * 68 + col + 1]       = acc[mt][nt][1];
                stage[(row + 8) * 68 + col]     = acc[mt][nt][2];
                stage[(row + 8) * 68 + col + 1] = acc[mt][nt][3];
            }
        __syncthreads();

        if (mi + 2 < 8) g0_load_A(sb, mbase + (mi + 2) * 128, tid, mi & 1);

#pragma unroll
        for (int i = 0; i < 8; i++) {
            int row = rb + i * 16;
            float4 v = *(const float4*)&stage[row * 68 + chl * 4];
            gate_store(v.x, v.y, v.z, v.w, na, (size_t)(m0 + row) * HID + chg);
        }
    }
}

// ======================= layer-1 GEMM: M-loop + K-chunked A, 3 CTAs/SM ========
// SMEM: W 64x256B @272 = 17408 | A bufs 2 x (128x128B @144 = 18432) | stage 64x68 f32
#define A1OFF   17408
#define ST1OFF  54272
#define SMEM1_BYTES 71680

// load A chunk: rows [m0,m0+128), fp8 bytes [kc*128, kc*128+128)
__device__ __forceinline__ void g1_load_A(uint32_t sb, int m0, int kc, int tid, int buf) {
    uint32_t dst = sb + A1OFF + buf * 18432;
    const uint8_t* src = g_A1 + (size_t)m0 * HID + kc * 128;
#pragma unroll
    for (int i = 0; i < 4; i++) {
        int idx = tid + i * 256;
        int row = idx >> 3, seg = idx & 7;
        CP16(dst + row * 144 + seg * 16, src + (size_t)row * HID + seg * 16);
    }
    CP_COMMIT();
}

__global__ void __launch_bounds__(256, 3) gemm1_kernel() {
    extern __shared__ __align__(16) char smem[];
    const uint32_t sb = smem_u32(smem);
    const int tid = threadIdx.x, lane = tid & 31;
    const int wm = (tid >> 5) >> 1, wn = (tid >> 5) & 1;
    const int n0 = blockIdx.x * 64;
    const int mbase = blockIdx.y * 1024;
    const int q = lane >> 3, r = lane & 7;

    // W load (full K)
#pragma unroll
    for (int i = 0; i < 4; i++) {
        int idx = tid + i * 256;
        int row = idx >> 4, seg = idx & 15;
        CP16(sb + row * 272 + seg * 16, g_W1 + (size_t)(n0 + row) * HID + seg * 16);
    }
    // prologue: chunk 0 (W rides in this group)
    g1_load_A(sb, mbase, 0, tid, 0);

    const uint32_t aoff = (uint32_t)(wm * 32 + (q & 1) * 8 + r) * 144 + (q >> 1) * 16;
    const uint32_t woff = (uint32_t)(wn * 32 + (q >> 1) * 8 + r) * 272 + (q & 1) * 16;
    const int chl = tid & 15;
    const int rb = tid >> 4;
    const int chg = blockIdx.x * 16 + chl;
    const float na = g_negA[HID + chg];
    float* stage = (float*)(smem + ST1OFF);
    const int whalf = wm >> 1;

    for (int mi = 0; mi < 8; mi++) {
        const int m0 = mbase + mi * 128;
        float acc[2][4][4];
#pragma unroll
        for (int mt = 0; mt < 2; mt++)
#pragma unroll
            for (int nt = 0; nt < 4; nt++)
#pragma unroll
                for (int i = 0; i < 4; i++) acc[mt][nt][i] = 0.f;

#pragma unroll
        for (int kc = 0; kc < 2; kc++) {
            const int c = mi * 2 + kc;          // chunk sequence index
            CP_WAIT(0);
            __syncthreads();                    // chunk c resident in buf c&1
            if (c + 1 < 16) {
                int nmi = (c + 1) >> 1, nkc = (c + 1) & 1;
                g1_load_A(sb, mbase + nmi * 128, nkc, tid, (c + 1) & 1);
            }

            const uint32_t abase = sb + A1OFF + (c & 1) * 18432;
#pragma unroll
            for (int ks = 0; ks < 4; ks++) {
                uint32_t ah[2][4];
#pragma unroll
                for (int mt = 0; mt < 2; mt++)
                    LDSM4(ah[mt], abase + aoff + (uint32_t)mt * (16 * 144) + ks * 32);
#pragma unroll
                for (int p = 0; p < 2; p++) {
                    uint32_t wh[4];
                    LDSM4(wh, sb + woff + (uint32_t)p * (16 * 272) + (kc * 4 + ks) * 32);
                    const int nt0 = p * 2, nt1 = p * 2 + 1;
                    MMA8(acc[0][nt0], ah[0], (wh + 0)); MMA8(acc[0][nt1], ah[0], (wh + 2));
                    MMA8(acc[1][nt0], ah[1], (wh + 0)); MMA8(acc[1][nt1], ah[1], (wh + 2));
                }
            }
            __syncthreads();                    // done reading buf c&1
        }

        // epilogue in two 64-row halves (half-size stage)
#pragma unroll
        for (int hhalf = 0; hhalf < 2; hhalf++) {
            if (whalf == hhalf) {
#pragma unroll
                for (int mt = 0; mt < 2; mt++)
#pragma unroll
                    for (int nt = 0; nt < 4; nt++) {
                        int row = (wm & 1) * 32 + mt * 16 + (lane >> 2);
                        int col = wn * 32 + nt * 8 + (lane & 3) * 2;
                        stage[row * 68 + col]           = acc[mt][nt][0];
                        stage[row * 68 + col + 1]       = acc[mt][nt][1];
                        stage[(row + 8) * 68 + col]     = acc[mt][nt][2];
                        stage[(row + 8) * 68 + col + 1] = acc[mt][nt][3];
                    }
            }
            __syncthreads();
#pragma unroll
            for (int i = 0; i < 4; i++) {
                int row = rb + i * 16;
                float4 v = *(const float4*)&stage[row * 68 + chl * 4];
                gate_store(v.x, v.y, v.z, v.w, na,
                           (size_t)(m0 + hhalf * 64 + row) * HID + chg);
            }
            __syncthreads();
        }
    }
}

// ======================= fused decoupled-lookback scan =======================
__device__ __forceinline__ float lookback_h0(int b, int h, float p, float s,
                                             float* Ph, float* Sh, float* Hin,
                                             int* flag) {
    __shared__ int smf[8];
    float h0 = 0.f;
    if (b > 0) {
        Ph[b * HID + h] = p;
        Sh[b * HID + h] = s;
        __syncthreads();
        __threadfence();
        if (h == 0) atomicExch(&flag[b], 1);

        float Pacc = 1.f, Sacc = 0.f;
        int j = b - 1;
        for (;;) {
            int w = (j + 1 < 8) ? (j + 1) : 8;
            if (h < w) {
                int f;
                do { f = atomicAdd(&flag[j - h], 0); } while (f == 0);
                smf[h] = f;
            }
            __syncthreads();
            int d2 = w;
            for (int d = 0; d < w; d++) if (smf[d] == 2) { d2 = d; break; }
            int nagg = (d2 < w) ? d2 : w;
            for (int d = 0; d < nagg; d++) {
                float P = __ldcg(&Ph[(size_t)(j - d) * HID + h]);
                float S = __ldcg(&Sh[(size_t)(j - d) * HID + h]);
                Sacc = fmaf(Pacc, S, Sacc);
                Pacc *= P;
            }
            if (d2 < w) {
                float H = __ldcg(&Hin[(size_t)(j - d2) * HID + h]);
                h0 = fmaf(Pacc, H, Sacc);
                break;
            }
            j -= w;
            if (j < 0) { h0 = Sacc; break; }
            __syncthreads();
        }
    }
    Hin[b * HID + h] = fmaf(p, h0, s);
    __syncthreads();
    __threadfence();
    if (h == 0) atomicExch(&flag[b], 2);
    return h0;
}

__global__ void __launch_bounds__(256) scan_l0_kernel() {
    int h = threadIdx.x, b = blockIdx.x;
    if (h == 0) atomicExch(&g_flag1[b], 0);
    size_t base = (size_t)b * 128 * HID + h;
    float p = 1.f, s = 0.f;
#pragma unroll 8
    for (int i = 0; i < 128; i++) {
        float2 f = __bfloat1622float2(g_ab[base + (size_t)i * HID]);
        p *= f.x;
        s = fmaf(f.x, s, f.y);
    }
    float hs = lookback_h0(b, h, p, s, g_Ph, g_Sh, g_Hin, g_flag0);
#pragma unroll 8
    for (int i = 0; i < 128; i++) {
        size_t o = base + (size_t)i * HID;
        float2 f = __bfloat1622float2(g_ab[o]);
        hs = fmaf(f.x, hs, f.y);
        float y = __bfloat162float(g_c[o]) * hs;
        g_A1[o] = to_fp8(y * SA);
    }
}

__global__ void __launch_bounds__(256) scan_l1_head_kernel(
        const float* __restrict__ Wout, const float* __restrict__ bout,
        float* __restrict__ out) {
    __shared__ float ws[4 * HID];
    __shared__ float bs4[4];
    __shared__ float yt[32][260];
    int tid = threadIdx.x, lane = tid & 31, w = tid >> 5;
    for (int i = tid; i < 4 * HID; i += 256) ws[i] = Wout[i];
    if (tid < 4) bs4[tid] = bout[tid];

    int h = tid, b = blockIdx.x;
    size_t base = (size_t)b * 128 * HID + h;
    float p = 1.f, s = 0.f;
#pragma unroll 8
    for (int i = 0; i < 128; i++) {
        float2 f = __bfloat1622float2(g_ab[base + (size_t)i * HID]);
        p *= f.x;
        s = fmaf(f.x, s, f.y);
    }
    float hs = lookback_h0(b, h, p, s, g_Ph, g_Sh, g_Hin, g_flag1);

    for (int sub = 0; sub < 4; sub++) {
#pragma unroll 8
        for (int j = 0; j < 32; j++) {
            size_t o = base + (size_t)(sub * 32 + j) * HID;
            float2 f = __bfloat1622float2(g_ab[o]);
            hs = fmaf(f.x, hs, f.y);
            yt[j][h] = __bfloat162float(g_c[o]) * hs;
        }
        __syncthreads();
#pragma unroll
        for (int tt = 0; tt < 4; tt++) {
            int tl = w * 4 + tt;
            float a0 = 0.f, a1 = 0.f, a2 = 0.f, a3 = 0.f;
#pragma unroll
            for (int k = 0; k < 8; k++) {
                float v = yt[tl][k * 32 + lane];
                a0 = fmaf(v, ws[0 * HID + k * 32 + lane], a0);
                a1 = fmaf(v, ws[1 * HID + k * 32 + lane], a1);
                a2 = fmaf(v, ws[2 * HID + k * 32 + lane], a2);
                a3 = fmaf(v, ws[3 * HID + k * 32 + lane], a3);
            }
#pragma unroll
            for (int o2 = 16; o2 > 0; o2 >>= 1) {
                a0 += __shfl_down_sync(0xFFFFFFFFu, a0, o2);
                a1 += __shfl_down_sync(0xFFFFFFFFu, a1, o2);
                a2 += __shfl_down_sync(0xFFFFFFFFu, a2, o2);
                a3 += __shfl_down_sync(0xFFFFFFFFu, a3, o2);
            }
            if (lane == 0) {
                float z[4] = {a0 + bs4[0], a1 + bs4[1], a2 + bs4[2], a3 + bs4[3]};
                size_t t = (size_t)b * 128 + sub * 32 + tl;
#pragma unroll
                for (int o3 = 0; o3 < 4; o3++) {
                    float zz = z[o3];
                    float sp = (zz > 20.f) ? zz : log1pf(expf(zz));
                    out[t * 4 + o3] = sp + 1.f;
                }
            }
        }
        __syncthreads();
    }
}

// ======================= launch =======================
extern "C" void kernel_launch(void* const* d_in, const int* in_sizes, int n_in,
                              void* d_out, int out_size) {
    const float* obs   = (const float*)d_in[0];
    const int*   act   = (const int*)  d_in[1];
    const float* emb   = (const float*)d_in[2];
    const float* Win0  = (const float*)d_in[3];
    const float* WB0   = (const float*)d_in[4];
    const float* WC0   = (const float*)d_in[5];
    const float* Wd0   = (const float*)d_in[6];
    const float* Alog0 = (const float*)d_in[7];
    const float* Win1  = (const float*)d_in[8];
    const float* WB1   = (const float*)d_in[9];
    const float* WC1   = (const float*)d_in[10];
    const float* Wd1   = (const float*)d_in[11];
    const float* Alog1 = (const float*)d_in[12];
    const float* Wout  = (const float*)d_in[13];
    const float* bout  = (const float*)d_in[14];
    float* out = (float*)d_out;

    cudaFuncSetAttribute(gemm0_kernel, cudaFuncAttributeMaxDynamicSharedMemorySize, SMEM0_BYTES);
    cudaFuncSetAttribute(gemm1_kernel, cudaFuncAttributeMaxDynamicSharedMemorySize, SMEM1_BYTES);

    prep_w_kernel<<<(NOUT * K0 + NOUT * HID) / 256, 256>>>(
        Win0, WB0, WC0, Wd0, Win1, WB1, WC1, Wd1);
    prep_a_kernel<<<1, 256>>>(Alog0, Alog1);
    build_x_kernel<<<T_LEN / 8, dim3(24, 8)>>>(obs, act, emb);

    dim3 ggrid(16, 64);

    gemm0_kernel<<<ggrid, 256, SMEM0_BYTES>>>();
    scan_l0_kernel<<<NH, HID>>>();

    gemm1_kernel<<<ggrid, 256, SMEM1_BYTES>>>();
    scan_l1_head_kernel<<<NH, HID>>>(Wout, bout, out);
}

// round 16
// speedup vs baseline: 1.1316x; 1.0446x over previous
#include <cuda_runtime.h>
#include <cuda_bf16.h>
#include <cuda_fp8.h>
#include <math.h>
#include <stdint.h>

#define T_LEN   65536
#define HID     256
#define K0      96          // layer-0 K (real 72) padded, fp8 elements
#define IN_RAW  72
#define NOUT    1024
#define NH      (T_LEN / 128)

#define SA      4.0f
#define SW      16.0f
#define INV_S   (1.0f / (SA * SW))

// ======================= scratch =======================
static __device__ uint8_t        g_A0[(size_t)T_LEN * K0];
static __device__ uint8_t        g_A1[(size_t)T_LEN * HID];
static __device__ uint8_t        g_W0[NOUT * K0];
static __device__ uint8_t        g_W1[NOUT * HID];
static __device__ __nv_bfloat162 g_ab[(size_t)T_LEN * HID];
static __device__ __nv_bfloat16  g_c [(size_t)T_LEN * HID];
static __device__ float g_Ph [NH * HID];
static __device__ float g_Sh [NH * HID];
static __device__ float g_Hin[NH * HID];
static __device__ int   g_flag0[NH];
static __device__ int   g_flag1[NH];
static __device__ float g_negA[2 * HID];

__device__ __forceinline__ uint32_t smem_u32(const void* p) {
    uint32_t a;
    asm("{ .reg .u64 t; cvta.to.shared.u64 t, %1; cvt.u32.u64 %0, t; }" : "=r"(a) : "l"(p));
    return a;
}
__device__ __forceinline__ uint8_t to_fp8(float v) {
    return (uint8_t)__nv_cvt_float_to_fp8(v, __NV_SATFINITE, __NV_E4M3);
}

#define CP16(so, gp) \
    asm volatile("cp.async.cg.shared.global [%0], [%1], 16;" :: "r"(so), "l"(gp) : "memory")
#define CP_COMMIT() asm volatile("cp.async.commit_group;" ::: "memory")
#define CP_WAIT(n)  asm volatile("cp.async.wait_group %0;" :: "n"(n) : "memory")

#define LDSM4(r, addr) \
    asm volatile("ldmatrix.sync.aligned.m8n8.x4.shared.b16 {%0,%1,%2,%3}, [%4];" \
        : "=r"((r)[0]), "=r"((r)[1]), "=r"((r)[2]), "=r"((r)[3]) : "r"(addr))

#define MMA8(d, a, b) \
    asm("mma.sync.aligned.m16n8k32.row.col.f32.e4m3.e4m3.f32 " \
        "{%0,%1,%2,%3}, {%4,%5,%6,%7}, {%8,%9}, {%0,%1,%2,%3};" \
        : "+f"((d)[0]), "+f"((d)[1]), "+f"((d)[2]), "+f"((d)[3]) \
        : "r"((a)[0]), "r"((a)[1]), "r"((a)[2]), "r"((a)[3]), \
          "r"((b)[0]), "r"((b)[1]))

// ======================= prep =======================
// j-major interleave: row r = (h>>3)*32 + j*8 + (h&7)
// so a warp's 8-col group nt == j, and (lane&3)*2 indexes channel-in-block.
__global__ void prep_w_kernel(const float* __restrict__ Win0, const float* __restrict__ WB0,
                              const float* __restrict__ WC0, const float* __restrict__ Wd0,
                              const float* __restrict__ Win1, const float* __restrict__ WB1,
                              const float* __restrict__ WC1, const float* __restrict__ Wd1) {
    int idx = blockIdx.x * 256 + threadIdx.x;
    if (idx < NOUT * K0) {
        int r = idx / K0, k = idx % K0;
        int j = (r >> 3) & 3;
        int h = (r >> 5) * 8 + (r & 7);
        float v = 0.f;
        if (k < IN_RAW) {
            const float* s = (j == 0) ? Win0 : (j == 1) ? WB0 : (j == 2) ? WC0 : Wd0;
            v = s[h * IN_RAW + k];
        }
        g_W0[idx] = to_fp8(v * SW);
    } else {
        int i2 = idx - NOUT * K0;
        int r = i2 / HID, k = i2 % HID;
        int j = (r >> 3) & 3;
        int h = (r >> 5) * 8 + (r & 7);
        const float* s = (j == 0) ? Win1 : (j == 1) ? WB1 : (j == 2) ? WC1 : Wd1;
        g_W1[i2] = to_fp8(s[h * HID + k] * SW);
    }
}

__global__ void prep_a_kernel(const float* __restrict__ A0, const float* __restrict__ A1) {
    int h = threadIdx.x;
    g_negA[h] = -expf(A0[h]);
    g_negA[HID + h] = -expf(A1[h]);
    g_flag0[h] = 0;
    g_flag0[h + 256] = 0;
}

__global__ void build_x_kernel(const float* __restrict__ obs, const int* __restrict__ act,
                               const float* __restrict__ emb) {
    int t  = blockIdx.x * 8 + threadIdx.y;
    int k4 = threadIdx.x;                              // 0..23
    float4 v = make_float4(0.f, 0.f, 0.f, 0.f);
    if (k4 < 16) {
        v = *(const float4*)&obs[(size_t)t * 64 + k4 * 4];
    } else if (k4 < 18) {
        int a = act[t];
        v = *(const float4*)&emb[a * 8 + (k4 - 16) * 4];
    }
    uint32_t o = (uint32_t)to_fp8(v.x * SA) | ((uint32_t)to_fp8(v.y * SA) << 8)
               | ((uint32_t)to_fp8(v.z * SA) << 16) | ((uint32_t)to_fp8(v.w * SA) << 24);
    *(uint32_t*)&g_A0[(size_t)t * K0 + k4 * 4] = o;
}

// register-direct gate epilogue: thread owns 2 adjacent channels (e=0,1) with all 4 j
__device__ __forceinline__ void gate_store2(const float acc[4][4], int mt_e_base,
                                            float na0, float na1, size_t o) {
    // mt_e_base = g*2 (g = 0: row, 1: row+8); e = +0 / +1
    // (indices into acc[j][g*2+e])
    float xs0 = acc[0][mt_e_base]     * INV_S, xs1 = acc[0][mt_e_base + 1] * INV_S;
    float B0  = acc[1][mt_e_base]     * INV_S, B1  = acc[1][mt_e_base + 1] * INV_S;
    float C0  = acc[2][mt_e_base]     * INV_S, C1  = acc[2][mt_e_base + 1] * INV_S;
    float d0  = acc[3][mt_e_base]     * INV_S, d1  = acc[3][mt_e_base + 1] * INV_S;
    float dl0 = __fdividef(1.f, 1.f + __expf(-d0));
    float dl1 = __fdividef(1.f, 1.f + __expf(-d1));
    float a0 = __expf(dl0 * na0), a1 = __expf(dl1 * na1);
    __nv_bfloat162 ab0 = __floats2bfloat162_rn(a0, B0 * xs0);
    __nv_bfloat162 ab1 = __floats2bfloat162_rn(a1, B1 * xs1);
    uint2 packed = make_uint2(*(uint32_t*)&ab0, *(uint32_t*)&ab1);
    *(uint2*)&g_ab[o] = packed;
    __nv_bfloat162 cc = __floats2bfloat162_rn(C0, C1);
    *(uint32_t*)&g_c[o] = *(uint32_t*)&cc;
}

// ======================= layer-0 GEMM: M-loop, K=96, stage-free epilogue ======
// SMEM: W 64x96B @112 = 7168 | A bufs 2 x 14336
#define A0OFF   7168
#define SMEM0_BYTES 35840

__device__ __forceinline__ void g0_load_A(uint32_t sb, int m0, int tid, int buf) {
    uint32_t dst = sb + A0OFF + buf * 14336;
#pragma unroll
    for (int i = 0; i < 3; i++) {
        int idx = tid + i * 256;
        int row = idx / 6, seg = idx % 6;
        CP16(dst + row * 112 + seg * 16, g_A0 + (size_t)(m0 + row) * K0 + seg * 16);
    }
    CP_COMMIT();
}

__global__ void __launch_bounds__(256, 3) gemm0_kernel() {
    extern __shared__ __align__(16) char smem[];
    const uint32_t sb = smem_u32(smem);
    const int tid = threadIdx.x, lane = tid & 31;
    const int wm = (tid >> 5) >> 1, wn = (tid >> 5) & 1;
    const int n0 = blockIdx.x * 64;
    const int mbase = blockIdx.y * 1024;
    const int q = lane >> 3, r = lane & 7;

#pragma unroll
    for (int i = 0; i < 2; i++) {
        int idx = tid + i * 256;
        if (idx < 384) {
            int row = idx / 6, seg = idx % 6;
            CP16(sb + row * 112 + seg * 16, g_W0 + (size_t)(n0 + row) * K0 + seg * 16);
        }
    }
    g0_load_A(sb, mbase, tid, 0);
    g0_load_A(sb, mbase + 128, tid, 1);

    const uint32_t aoff = (uint32_t)(wm * 32 + (q & 1) * 8 + r) * 112 + (q >> 1) * 16;
    const uint32_t woff = (uint32_t)(wn * 32 + (q >> 1) * 8 + r) * 112 + (q & 1) * 16;
    const int ch = blockIdx.x * 16 + wn * 8 + (lane & 3) * 2;
    const float na0 = g_negA[ch], na1 = g_negA[ch + 1];

    for (int mi = 0; mi < 8; mi++) {
        const int m0 = mbase + mi * 128;
        if (mi == 7) { CP_WAIT(0); } else { CP_WAIT(1); }
        __syncthreads();

        float acc[2][4][4];
#pragma unroll
        for (int mt = 0; mt < 2; mt++)
#pragma unroll
            for (int nt = 0; nt < 4; nt++)
#pragma unroll
                for (int i = 0; i < 4; i++) acc[mt][nt][i] = 0.f;

        const uint32_t abase = sb + A0OFF + (mi & 1) * 14336;
#pragma unroll
        for (int ks = 0; ks < 3; ks++) {
            uint32_t ah[2][4];
#pragma unroll
            for (int mt = 0; mt < 2; mt++)
                LDSM4(ah[mt], abase + aoff + (uint32_t)mt * (16 * 112) + ks * 32);
#pragma unroll
            for (int p = 0; p < 2; p++) {
                uint32_t wh[4];
                LDSM4(wh, sb + woff + (uint32_t)p * (16 * 112) + ks * 32);
                const int nt0 = p * 2, nt1 = p * 2 + 1;
                MMA8(acc[0][nt0], ah[0], (wh + 0)); MMA8(acc[0][nt1], ah[0], (wh + 2));
                MMA8(acc[1][nt0], ah[1], (wh + 0)); MMA8(acc[1][nt1], ah[1], (wh + 2));
            }
        }
        __syncthreads();                    // all warps done reading buf mi&1
        if (mi + 2 < 8) g0_load_A(sb, mbase + (mi + 2) * 128, tid, mi & 1);

        // register-direct epilogue
#pragma unroll
        for (int mt = 0; mt < 2; mt++) {
            int row = wm * 32 + mt * 16 + (lane >> 2);
#pragma unroll
            for (int g = 0; g < 2; g++) {
                size_t o = (size_t)(m0 + row + g * 8) * HID + ch;
                gate_store2(acc[mt], g * 2, na0, na1, o);
            }
        }
    }
}

// ======================= layer-1 GEMM: M-loop + K-chunked A, stage-free =======
// SMEM: W 64x256B @272 = 17408 | A bufs 2 x 18432
#define A1OFF   17408
#define SMEM1_BYTES 54272

__device__ __forceinline__ void g1_load_A(uint32_t sb, int m0, int kc, int tid, int buf) {
    uint32_t dst = sb + A1OFF + buf * 18432;
    const uint8_t* src = g_A1 + (size_t)m0 * HID + kc * 128;
#pragma unroll
    for (int i = 0; i < 4; i++) {
        int idx = tid + i * 256;
        int row = idx >> 3, seg = idx & 7;
        CP16(dst + row * 144 + seg * 16, src + (size_t)row * HID + seg * 16);
    }
    CP_COMMIT();
}

__global__ void __launch_bounds__(256, 3) gemm1_kernel() {
    extern __shared__ __align__(16) char smem[];
    const uint32_t sb = smem_u32(smem);
    const int tid = threadIdx.x, lane = tid & 31;
    const int wm = (tid >> 5) >> 1, wn = (tid >> 5) & 1;
    const int n0 = blockIdx.x * 64;
    const int mbase = blockIdx.y * 1024;
    const int q = lane >> 3, r = lane & 7;

#pragma unroll
    for (int i = 0; i < 4; i++) {
        int idx = tid + i * 256;
        int row = idx >> 4, seg = idx & 15;
        CP16(sb + row * 272 + seg * 16, g_W1 + (size_t)(n0 + row) * HID + seg * 16);
    }
    g1_load_A(sb, mbase, 0, tid, 0);

    const uint32_t aoff = (uint32_t)(wm * 32 + (q & 1) * 8 + r) * 144 + (q >> 1) * 16;
    const uint32_t woff = (uint32_t)(wn * 32 + (q >> 1) * 8 + r) * 272 + (q & 1) * 16;
    const int ch = blockIdx.x * 16 + wn * 8 + (lane & 3) * 2;
    const float na0 = g_negA[HID + ch], na1 = g_negA[HID + ch + 1];

    for (int mi = 0; mi < 8; mi++) {
        const int m0 = mbase + mi * 128;
        float acc[2][4][4];
#pragma unroll
        for (int mt = 0; mt < 2; mt++)
#pragma unroll
            for (int nt = 0; nt < 4; nt++)
#pragma unroll
                for (int i = 0; i < 4; i++) acc[mt][nt][i] = 0.f;

#pragma unroll
        for (int kc = 0; kc < 2; kc++) {
            const int c = mi * 2 + kc;
            CP_WAIT(0);
            __syncthreads();
            if (c + 1 < 16) {
                int nmi = (c + 1) >> 1, nkc = (c + 1) & 1;
                g1_load_A(sb, mbase + nmi * 128, nkc, tid, (c + 1) & 1);
            }

            const uint32_t abase = sb + A1OFF + (c & 1) * 18432;
#pragma unroll
            for (int ks = 0; ks < 4; ks++) {
                uint32_t ah[2][4];
#pragma unroll
                for (int mt = 0; mt < 2; mt++)
                    LDSM4(ah[mt], abase + aoff + (uint32_t)mt * (16 * 144) + ks * 32);
#pragma unroll
                for (int p = 0; p < 2; p++) {
                    uint32_t wh[4];
                    LDSM4(wh, sb + woff + (uint32_t)p * (16 * 272) + (kc * 4 + ks) * 32);
                    const int nt0 = p * 2, nt1 = p * 2 + 1;
                    MMA8(acc[0][nt0], ah[0], (wh + 0)); MMA8(acc[0][nt1], ah[0], (wh + 2));
                    MMA8(acc[1][nt0], ah[1], (wh + 0)); MMA8(acc[1][nt1], ah[1], (wh + 2));
                }
            }
            __syncthreads();
        }

        // register-direct epilogue
#pragma unroll
        for (int mt = 0; mt < 2; mt++) {
            int row = wm * 32 + mt * 16 + (lane >> 2);
#pragma unroll
            for (int g = 0; g < 2; g++) {
                size_t o = (size_t)(m0 + row + g * 8) * HID + ch;
                gate_store2(acc[mt], g * 2, na0, na1, o);
            }
        }
    }
}

// ======================= fused decoupled-lookback scan =======================
__device__ __forceinline__ float lookback_h0(int b, int h, float p, float s,
                                             float* Ph, float* Sh, float* Hin,
                                             int* flag) {
    __shared__ int smf[8];
    float h0 = 0.f;
    if (b > 0) {
        Ph[b * HID + h] = p;
        Sh[b * HID + h] = s;
        __syncthreads();
        __threadfence();
        if (h == 0) atomicExch(&flag[b], 1);

        float Pacc = 1.f, Sacc = 0.f;
        int j = b - 1;
        for (;;) {
            int w = (j + 1 < 8) ? (j + 1) : 8;
            if (h < w) {
                int f;
                do { f = atomicAdd(&flag[j - h], 0); } while (f == 0);
                smf[h] = f;
            }
            __syncthreads();
            int d2 = w;
            for (int d = 0; d < w; d++) if (smf[d] == 2) { d2 = d; break; }
            int nagg = (d2 < w) ? d2 : w;
            for (int d = 0; d < nagg; d++) {
                float P = __ldcg(&Ph[(size_t)(j - d) * HID + h]);
                float S = __ldcg(&Sh[(size_t)(j - d) * HID + h]);
                Sacc = fmaf(Pacc, S, Sacc);
                Pacc *= P;
            }
            if (d2 < w) {
                float H = __ldcg(&Hin[(size_t)(j - d2) * HID + h]);
                h0 = fmaf(Pacc, H, Sacc);
                break;
            }
            j -= w;
            if (j < 0) { h0 = Sacc; break; }
            __syncthreads();
        }
    }
    Hin[b * HID + h] = fmaf(p, h0, s);
    __syncthreads();
    __threadfence();
    if (h == 0) atomicExch(&flag[b], 2);
    return h0;
}

__global__ void __launch_bounds__(256) scan_l0_kernel() {
    int h = threadIdx.x, b = blockIdx.x;
    if (h == 0) atomicExch(&g_flag1[b], 0);
    size_t base = (size_t)b * 128 * HID + h;
    float p = 1.f, s = 0.f;
#pragma unroll 8
    for (int i = 0; i < 128; i++) {
        float2 f = __bfloat1622float2(g_ab[base + (size_t)i * HID]);
        p *= f.x;
        s = fmaf(f.x, s, f.y);
    }
    float hs = lookback_h0(b, h, p, s, g_Ph, g_Sh, g_Hin, g_flag0);
#pragma unroll 8
    for (int i = 0; i < 128; i++) {
        size_t o = base + (size_t)i * HID;
        float2 f = __bfloat1622float2(g_ab[o]);
        hs = fmaf(f.x, hs, f.y);
        float y = __bfloat162float(g_c[o]) * hs;
        g_A1[o] = to_fp8(y * SA);
    }
}

__global__ void __launch_bounds__(256) scan_l1_head_kernel(
        const float* __restrict__ Wout, const float* __restrict__ bout,
        float* __restrict__ out) {
    __shared__ float ws[4 * HID];
    __shared__ float bs4[4];
    __shared__ float yt[32][260];
    int tid = threadIdx.x, lane = tid & 31, w = tid >> 5;
    for (int i = tid; i < 4 * HID; i += 256) ws[i] = Wout[i];
    if (tid < 4) bs4[tid] = bout[tid];

    int h = tid, b = blockIdx.x;
    size_t base = (size_t)b * 128 * HID + h;
    float p = 1.f, s = 0.f;
#pragma unroll 8
    for (int i = 0; i < 128; i++) {
        float2 f = __bfloat1622float2(g_ab[base + (size_t)i * HID]);
        p *= f.x;
        s = fmaf(f.x, s, f.y);
    }
    float hs = lookback_h0(b, h, p, s, g_Ph, g_Sh, g_Hin, g_flag1);

    for (int sub = 0; sub < 4; sub++) {
#pragma unroll 8
        for (int j = 0; j < 32; j++) {
            size_t o = base + (size_t)(sub * 32 + j) * HID;
            float2 f = __bfloat1622float2(g_ab[o]);
            hs = fmaf(f.x, hs, f.y);
            yt[j][h] = __bfloat162float(g_c[o]) * hs;
        }
        __syncthreads();
#pragma unroll
        for (int tt = 0; tt < 4; tt++) {
            int tl = w * 4 + tt;
            float a0 = 0.f, a1 = 0.f, a2 = 0.f, a3 = 0.f;
#pragma unroll
            for (int k = 0; k < 8; k++) {
                float v = yt[tl][k * 32 + lane];
                a0 = fmaf(v, ws[0 * HID + k * 32 + lane], a0);
                a1 = fmaf(v, ws[1 * HID + k * 32 + lane], a1);
                a2 = fmaf(v, ws[2 * HID + k * 32 + lane], a2);
                a3 = fmaf(v, ws[3 * HID + k * 32 + lane], a3);
            }
#pragma unroll
            for (int o2 = 16; o2 > 0; o2 >>= 1) {
                a0 += __shfl_down_sync(0xFFFFFFFFu, a0, o2);
                a1 += __shfl_down_sync(0xFFFFFFFFu, a1, o2);
                a2 += __shfl_down_sync(0xFFFFFFFFu, a2, o2);
                a3 += __shfl_down_sync(0xFFFFFFFFu, a3, o2);
            }
            if (lane == 0) {
                float z[4] = {a0 + bs4[0], a1 + bs4[1], a2 + bs4[2], a3 + bs4[3]};
                size_t t = (size_t)b * 128 + sub * 32 + tl;
#pragma unroll
                for (int o3 = 0; o3 < 4; o3++) {
                    float zz = z[o3];
                    float sp = (zz > 20.f) ? zz : log1pf(expf(zz));
                    out[t * 4 + o3] = sp + 1.f;
                }
            }
        }
        __syncthreads();
    }
}

// ======================= launch =======================
extern "C" void kernel_launch(void* const* d_in, const int* in_sizes, int n_in,
                              void* d_out, int out_size) {
    const float* obs   = (const float*)d_in[0];
    const int*   act   = (const int*)  d_in[1];
    const float* emb   = (const float*)d_in[2];
    const float* Win0  = (const float*)d_in[3];
    const float* WB0   = (const float*)d_in[4];
    const float* WC0   = (const float*)d_in[5];
    const float* Wd0   = (const float*)d_in[6];
    const float* Alog0 = (const float*)d_in[7];
    const float* Win1  = (const float*)d_in[8];
    const float* WB1   = (const float*)d_in[9];
    const float* WC1   = (const float*)d_in[10];
    const float* Wd1   = (const float*)d_in[11];
    const float* Alog1 = (const float*)d_in[12];
    const float* Wout  = (const float*)d_in[13];
    const float* bout  = (const float*)d_in[14];
    float* out = (float*)d_out;

    cudaFuncSetAttribute(gemm0_kernel, cudaFuncAttributeMaxDynamicSharedMemorySize, SMEM0_BYTES);
    cudaFuncSetAttribute(gemm1_kernel, cudaFuncAttributeMaxDynamicSharedMemorySize, SMEM1_BYTES);

    prep_w_kernel<<<(NOUT * K0 + NOUT * HID) / 256, 256>>>(
        Win0, WB0, WC0, Wd0, Win1, WB1, WC1, Wd1);
    prep_a_kernel<<<1, 256>>>(Alog0, Alog1);
    build_x_kernel<<<T_LEN / 8, dim3(24, 8)>>>(obs, act, emb);

    dim3 ggrid(16, 64);

    gemm0_kernel<<<ggrid, 256, SMEM0_BYTES>>>();
    scan_l0_kernel<<<NH, HID>>>();

    gemm1_kernel<<<ggrid, 256, SMEM1_BYTES>>>();
    scan_l1_head_kernel<<<NH, HID>>>(Wout, bout, out);
}